// round 3
// baseline (speedup 1.0000x reference)
#include <cuda_runtime.h>
#include <math.h>

#define D_   2048
#define H_   16
#define HD_  128
#define B_   2
#define T_   2048
#define NT_  (B_*T_)          // 4096 tokens
#define EPS_ 1e-6f

// ---------------- scratch (static device arrays; no allocation allowed) ----
__device__ float g_h  [(size_t)NT_ * D_];        // 32 MB  rmsnorm output
__device__ float g_qkv[(size_t)NT_ * 3 * D_];    // 96 MB  qkv (rope applied in place)
__device__ float g_y  [(size_t)NT_ * D_];        // 32 MB  attention output
__device__ float g_x1 [(size_t)NT_ * D_];        // 32 MB  x + attn proj
__device__ float g_h2 [(size_t)NT_ * 4 * D_];    // 128 MB fc1 output

// ---------------------------------------------------------------- rmsnorm --
__global__ void rmsnorm_kernel(const float* __restrict__ x,
                               const float* __restrict__ w,
                               float* __restrict__ out)
{
    const int row = blockIdx.x;
    const float* xr = x + (size_t)row * D_;
    float ss = 0.f;
    for (int i = threadIdx.x; i < D_; i += blockDim.x) {
        float v = xr[i];
        ss += v * v;
    }
    __shared__ float red[32];
    #pragma unroll
    for (int o = 16; o; o >>= 1) ss += __shfl_xor_sync(0xffffffffu, ss, o);
    if ((threadIdx.x & 31) == 0) red[threadIdx.x >> 5] = ss;
    __syncthreads();
    if (threadIdx.x < 32) {
        float v = (threadIdx.x < (blockDim.x >> 5)) ? red[threadIdx.x] : 0.f;
        #pragma unroll
        for (int o = 16; o; o >>= 1) v += __shfl_xor_sync(0xffffffffu, v, o);
        if (threadIdx.x == 0) red[0] = v;
    }
    __syncthreads();
    const float n   = sqrtf(red[0]) * rsqrtf((float)D_); // sqrt(sum x^2) * D^-0.5
    const float inv = 1.f / (n + EPS_);
    float* orow = out + (size_t)row * D_;
    for (int i = threadIdx.x; i < D_; i += blockDim.x)
        orow[i] = xr[i] * inv * w[i];
}

// ------------------------------------------------------------------- gemm --
// C[M,N] = A[M,K] @ B[K,N] + bias, with epilogue:
//   EPI=0: bias only   EPI=1: bias + SiLU   EPI=2: bias + residual
// 128x128 tile, BK=16, 256 threads, 8x8 per thread.
template<int EPI>
__global__ void __launch_bounds__(256)
gemm_kernel(const float* __restrict__ A, const float* __restrict__ Bm,
            const float* __restrict__ bias, const float* __restrict__ res,
            float* __restrict__ C, int M, int N, int K)
{
    __shared__ float As[16][128];   // transposed: As[k][m]
    __shared__ float Bs[16][128];   // Bs[k][n]

    const int tid = threadIdx.x;
    const int bm  = blockIdx.y * 128;
    const int bn  = blockIdx.x * 128;
    const int ty  = tid >> 4;       // 0..15 (rows)
    const int tx  = tid & 15;       // 0..15 (cols)

    float acc[8][8];
    #pragma unroll
    for (int i = 0; i < 8; i++)
        #pragma unroll
        for (int j = 0; j < 8; j++) acc[i][j] = 0.f;

    const float* Ab = A  + (size_t)bm * K;
    const float* Bb = Bm + bn;

    for (int k0 = 0; k0 < K; k0 += 16) {
        // A tile 128x16 -> As[k][m]  (512 float4, 2 per thread)
        #pragma unroll
        for (int i = 0; i < 2; i++) {
            int idx = tid + i * 256;
            int r   = idx >> 2;           // 0..127
            int kq  = (idx & 3) << 2;     // 0,4,8,12
            float4 v = *(const float4*)(Ab + (size_t)r * K + (k0 + kq));
            As[kq + 0][r] = v.x; As[kq + 1][r] = v.y;
            As[kq + 2][r] = v.z; As[kq + 3][r] = v.w;
        }
        // B tile 16x128 -> Bs[k][n]
        #pragma unroll
        for (int i = 0; i < 2; i++) {
            int idx = tid + i * 256;
            int r   = idx >> 5;           // 0..15
            int c   = (idx & 31) << 2;    // 0..124
            *(float4*)&Bs[r][c] = *(const float4*)(Bb + (size_t)(k0 + r) * N + c);
        }
        __syncthreads();

        #pragma unroll
        for (int kk = 0; kk < 16; kk++) {
            float a[8], b[8];
            *(float4*)&a[0] = *(const float4*)&As[kk][ty * 8];
            *(float4*)&a[4] = *(const float4*)&As[kk][ty * 8 + 4];
            // split-column B frag: cols tx*4..+3 and 64+tx*4..+3 (conflict-free)
            *(float4*)&b[0] = *(const float4*)&Bs[kk][tx * 4];
            *(float4*)&b[4] = *(const float4*)&Bs[kk][64 + tx * 4];
            #pragma unroll
            for (int i = 0; i < 8; i++)
                #pragma unroll
                for (int j = 0; j < 8; j++)
                    acc[i][j] = fmaf(a[i], b[j], acc[i][j]);
        }
        __syncthreads();
    }

    // epilogue
    #pragma unroll
    for (int i = 0; i < 8; i++) {
        size_t row = (size_t)(bm + ty * 8 + i);
        float* crow = C + row * (size_t)N;
        #pragma unroll
        for (int g = 0; g < 2; g++) {
            int col = bn + g * 64 + tx * 4;
            float4 bv = *(const float4*)(bias + col);
            float4 v;
            v.x = acc[i][g * 4 + 0] + bv.x;
            v.y = acc[i][g * 4 + 1] + bv.y;
            v.z = acc[i][g * 4 + 2] + bv.z;
            v.w = acc[i][g * 4 + 3] + bv.w;
            if (EPI == 1) {  // SiLU
                v.x = v.x / (1.f + expf(-v.x));
                v.y = v.y / (1.f + expf(-v.y));
                v.z = v.z / (1.f + expf(-v.z));
                v.w = v.w / (1.f + expf(-v.w));
            }
            if (EPI == 2) {  // residual
                float4 rv = *(const float4*)(res + row * (size_t)N + col);
                v.x += rv.x; v.y += rv.y; v.z += rv.z; v.w += rv.w;
            }
            *(float4*)(crow + col) = v;
        }
    }
}

// ------------------------------------------------------------------- rope --
// In-place RoPE on q and k halves of the qkv buffer.
__global__ void rope_kernel(float* __restrict__ qkv)
{
    const int half = HD_ / 2;                    // 64
    const int per  = NT_ * H_ * half;            // elements per (q|k)
    int idx = blockIdx.x * blockDim.x + threadIdx.x;
    if (idx >= 2 * per) return;
    const int which = idx / per;                 // 0 = q, 1 = k
    int rem   = idx - which * per;
    const int tok = rem / (H_ * half);
    const int hh  = (rem / half) % H_;
    const int d   = rem % half;
    const int t   = tok % T_;                    // position within sequence

    // compute angle in fp64 (stays within fp32-reference error budget)
    double rate  = pow(10000.0, -2.0 * (double)d / (double)HD_);
    double theta = (double)t * rate;
    double sd, cd;
    sincos(theta, &sd, &cd);
    const float s = (float)sd, c = (float)cd;

    float* base = qkv + (size_t)tok * (3 * D_) + (size_t)which * D_ + hh * HD_;
    float x1v = base[d];
    float x2v = base[d + half];
    base[d]        = x1v * c - x2v * s;
    base[d + half] = x1v * s + x2v * c;
}

// -------------------------------------------------------- flash attention --
// grid (T/64, B*H), 128 threads. BQ = BK = 64, online softmax.
// Smem: Qs[d][r] (transposed), Ks[d][r] (transposed), Vs[r][d], Pt[c][r].
#define PT_STRIDE 68
#define ATTN_SMEM ((128*64 + 128*64 + 64*128 + 64*PT_STRIDE) * 4)

__global__ void __launch_bounds__(128)
attn_kernel(const float* __restrict__ qkv, float* __restrict__ y)
{
    extern __shared__ float sm[];
    float* Qs = sm;                      // [128][64]
    float* Ks = sm + 128 * 64;           // [128][64]
    float* Vs = Ks + 128 * 64;           // [64][128]
    float* Pt = Vs + 64 * 128;           // [64][PT_STRIDE]

    const int qb  = blockIdx.x;          // q block (64 rows)
    const int bh  = blockIdx.y;
    const int b   = bh >> 4;             // H_=16
    const int h   = bh & 15;
    const int tid = threadIdx.x;
    const int ty  = tid >> 3;            // 0..15 -> rows ty*4..+3
    const int tx  = tid & 7;             // 0..7  -> col groups

    const size_t rs = 3 * D_;            // qkv row stride (6144)
    const float* qbase = qkv + ((size_t)(b * T_ + qb * 64)) * rs + h * HD_;

    // load Q transposed: Qs[d][r]
    #pragma unroll
    for (int it = 0; it < 16; it++) {
        int idx = tid + it * 128;        // 0..2047
        int r   = idx >> 5;              // 0..63
        int d4  = (idx & 31) << 2;       // 0..124
        float4 v = *(const float4*)(qbase + (size_t)r * rs + d4);
        Qs[(d4 + 0) * 64 + r] = v.x;
        Qs[(d4 + 1) * 64 + r] = v.y;
        Qs[(d4 + 2) * 64 + r] = v.z;
        Qs[(d4 + 3) * 64 + r] = v.w;
    }

    float o[4][16];
    #pragma unroll
    for (int i = 0; i < 4; i++)
        #pragma unroll
        for (int j = 0; j < 16; j++) o[i][j] = 0.f;
    float m[4], l[4];
    #pragma unroll
    for (int i = 0; i < 4; i++) { m[i] = -1e30f; l[i] = 0.f; }

    const float scale = 0.08838834764831843f;   // HD^-0.5

    for (int kb = 0; kb <= qb; kb++) {
        __syncthreads();   // previous PV done reading Ks/Vs/Pt
        const float* kbase = qkv + ((size_t)(b * T_ + kb * 64)) * rs + D_ + h * HD_;
        const float* vbase = kbase + D_;
        #pragma unroll
        for (int it = 0; it < 16; it++) {
            int idx = tid + it * 128;
            int r   = idx >> 5;
            int d4  = (idx & 31) << 2;
            float4 kv = *(const float4*)(kbase + (size_t)r * rs + d4);
            Ks[(d4 + 0) * 64 + r] = kv.x;
            Ks[(d4 + 1) * 64 + r] = kv.y;
            Ks[(d4 + 2) * 64 + r] = kv.z;
            Ks[(d4 + 3) * 64 + r] = kv.w;
            float4 vv = *(const float4*)(vbase + (size_t)r * rs + d4);
            *(float4*)&Vs[r * 128 + d4] = vv;
        }
        __syncthreads();

        // S = Q @ K^T : thread tile 4 rows x 8 cols (split 0..31 / 32..63)
        float s[4][8];
        #pragma unroll
        for (int i = 0; i < 4; i++)
            #pragma unroll
            for (int j = 0; j < 8; j++) s[i][j] = 0.f;
        #pragma unroll 4
        for (int kk = 0; kk < 128; kk++) {
            float4 qa = *(const float4*)&Qs[kk * 64 + ty * 4];
            float4 ka = *(const float4*)&Ks[kk * 64 + tx * 4];
            float4 kh = *(const float4*)&Ks[kk * 64 + 32 + tx * 4];
            float qv[4] = {qa.x, qa.y, qa.z, qa.w};
            float kv8[8] = {ka.x, ka.y, ka.z, ka.w, kh.x, kh.y, kh.z, kh.w};
            #pragma unroll
            for (int i = 0; i < 4; i++)
                #pragma unroll
                for (int j = 0; j < 8; j++)
                    s[i][j] = fmaf(qv[i], kv8[j], s[i][j]);
        }

        // scale + causal mask (diagonal tile only)
        const bool diag = (kb == qb);
        #pragma unroll
        for (int i = 0; i < 4; i++) {
            int rloc = ty * 4 + i;
            #pragma unroll
            for (int j = 0; j < 8; j++) {
                float v = s[i][j] * scale;
                if (diag) {
                    int c = (j < 4) ? (tx * 4 + j) : (32 + tx * 4 + (j - 4));
                    if (c > rloc) v = -1e30f;
                }
                s[i][j] = v;
            }
        }

        // online softmax (row stats shared across the 8-lane tx group)
        #pragma unroll
        for (int i = 0; i < 4; i++) {
            float rm = s[i][0];
            #pragma unroll
            for (int j = 1; j < 8; j++) rm = fmaxf(rm, s[i][j]);
            rm = fmaxf(rm, __shfl_xor_sync(0xffffffffu, rm, 1));
            rm = fmaxf(rm, __shfl_xor_sync(0xffffffffu, rm, 2));
            rm = fmaxf(rm, __shfl_xor_sync(0xffffffffu, rm, 4));
            float mn   = fmaxf(m[i], rm);
            float corr = expf(m[i] - mn);
            float rsum = 0.f;
            #pragma unroll
            for (int j = 0; j < 8; j++) {
                float p = expf(s[i][j] - mn);
                s[i][j] = p;
                rsum += p;
            }
            rsum += __shfl_xor_sync(0xffffffffu, rsum, 1);
            rsum += __shfl_xor_sync(0xffffffffu, rsum, 2);
            rsum += __shfl_xor_sync(0xffffffffu, rsum, 4);
            l[i] = l[i] * corr + rsum;
            m[i] = mn;
            #pragma unroll
            for (int j = 0; j < 16; j++) o[i][j] *= corr;
        }

        // store P transposed: Pt[c][r]
        #pragma unroll
        for (int j = 0; j < 8; j++) {
            int c = (j < 4) ? (tx * 4 + j) : (32 + tx * 4 + (j - 4));
            float4 pv = make_float4(s[0][j], s[1][j], s[2][j], s[3][j]);
            *(float4*)&Pt[c * PT_STRIDE + ty * 4] = pv;
        }
        __syncthreads();

        // O += P @ V : thread cols jj*32 + tx*4 + cc
        #pragma unroll 2
        for (int j = 0; j < 64; j++) {
            float4 p4 = *(const float4*)&Pt[j * PT_STRIDE + ty * 4];
            float pv[4] = {p4.x, p4.y, p4.z, p4.w};
            #pragma unroll
            for (int jj = 0; jj < 4; jj++) {
                float4 v4 = *(const float4*)&Vs[j * 128 + jj * 32 + tx * 4];
                float vv[4] = {v4.x, v4.y, v4.z, v4.w};
                #pragma unroll
                for (int i = 0; i < 4; i++)
                    #pragma unroll
                    for (int cc = 0; cc < 4; cc++)
                        o[i][jj * 4 + cc] = fmaf(pv[i], vv[cc], o[i][jj * 4 + cc]);
            }
        }
    }

    // write y[(b*T + t), h*HD + col]
    #pragma unroll
    for (int i = 0; i < 4; i++) {
        float invl = 1.f / l[i];
        size_t row = (size_t)(b * T_ + qb * 64 + ty * 4 + i);
        float* yrow = y + row * D_ + h * HD_;
        #pragma unroll
        for (int jj = 0; jj < 4; jj++) {
            float4 v;
            v.x = o[i][jj * 4 + 0] * invl;
            v.y = o[i][jj * 4 + 1] * invl;
            v.z = o[i][jj * 4 + 2] * invl;
            v.w = o[i][jj * 4 + 3] * invl;
            *(float4*)(yrow + jj * 32 + tx * 4) = v;
        }
    }
}

// ------------------------------------------------------------------- host --
extern "C" void kernel_launch(void* const* d_in, const int* in_sizes, int n_in,
                              void* d_out, int out_size)
{
    const float* x       = (const float*)d_in[0];
    // d_in[1] = causal mask (tril) — structure known, not read
    const float* w_norm1 = (const float*)d_in[2];
    const float* w_qkv   = (const float*)d_in[3];
    const float* b_qkv   = (const float*)d_in[4];
    const float* w_proj  = (const float*)d_in[5];
    const float* b_proj  = (const float*)d_in[6];
    const float* w_norm2 = (const float*)d_in[7];
    const float* w_fc1   = (const float*)d_in[8];
    const float* b_fc1   = (const float*)d_in[9];
    const float* w_fc2   = (const float*)d_in[10];
    const float* b_fc2   = (const float*)d_in[11];
    float* out = (float*)d_out;

    float *h, *qkv, *y, *x1, *h2;
    cudaGetSymbolAddress((void**)&h,   g_h);
    cudaGetSymbolAddress((void**)&qkv, g_qkv);
    cudaGetSymbolAddress((void**)&y,   g_y);
    cudaGetSymbolAddress((void**)&x1,  g_x1);
    cudaGetSymbolAddress((void**)&h2,  g_h2);

    cudaFuncSetAttribute(attn_kernel,
                         cudaFuncAttributeMaxDynamicSharedMemorySize, ATTN_SMEM);

    // 1. h = rmsnorm(x, w_norm1)
    rmsnorm_kernel<<<NT_, 256>>>(x, w_norm1, h);
    // 2. qkv = h @ w_qkv + b_qkv
    gemm_kernel<0><<<dim3(3 * D_ / 128, NT_ / 128), 256>>>(
        h, w_qkv, b_qkv, nullptr, qkv, NT_, 3 * D_, D_);
    // 3. rope(q, k) in place
    rope_kernel<<<(2 * NT_ * H_ * (HD_ / 2)) / 256, 256>>>(qkv);
    // 4. y = causal attention
    attn_kernel<<<dim3(T_ / 64, B_ * H_), 128, ATTN_SMEM>>>(qkv, y);
    // 5. x1 = x + (y @ w_proj + b_proj)
    gemm_kernel<2><<<dim3(D_ / 128, NT_ / 128), 256>>>(
        y, w_proj, b_proj, x, x1, NT_, D_, D_);
    // 6. h = rmsnorm(x1, w_norm2)
    rmsnorm_kernel<<<NT_, 256>>>(x1, w_norm2, h);
    // 7. h2 = silu(h @ w_fc1 + b_fc1)
    gemm_kernel<1><<<dim3(4 * D_ / 128, NT_ / 128), 256>>>(
        h, w_fc1, b_fc1, nullptr, h2, NT_, 4 * D_, D_);
    // 8. out = x1 + (h2 @ w_fc2 + b_fc2)
    gemm_kernel<2><<<dim3(D_ / 128, NT_ / 128), 256>>>(
        h2, w_fc2, b_fc2, x1, out, NT_, D_, 4 * D_);
}

// round 7
// speedup vs baseline: 1.5017x; 1.5017x over previous
#include <cuda_runtime.h>
#include <cuda_bf16.h>
#include <math.h>
#include <stdint.h>

#define D_   2048
#define H_   16
#define HD_  128
#define B_   2
#define T_   2048
#define NT_  (B_*T_)          // 4096 tokens
#define EPS_ 1e-6f

// ---------------- scratch (static device arrays; no allocation allowed) ----
__device__ float g_h  [(size_t)NT_ * D_];        // 32 MB  rmsnorm output
__device__ float g_qkv[(size_t)NT_ * 3 * D_];    // 96 MB  qkv (rope applied in place)
__device__ float g_y  [(size_t)NT_ * D_];        // 32 MB  attention output
__device__ float g_x1 [(size_t)NT_ * D_];        // 32 MB  x + attn proj
__device__ float g_h2 [(size_t)NT_ * 4 * D_];    // 128 MB fc1 output

// ---------------------------------------------------------------- helpers --
__device__ __forceinline__ uint32_t sptr(const void* p) {
    return (uint32_t)__cvta_generic_to_shared(p);
}

// split two fp32 into packed bf16 hi / lo pairs (lo = residual)
__device__ __forceinline__ void split2(float x, float y, uint32_t& hp, uint32_t& lp) {
    __nv_bfloat16 hx = __float2bfloat16(x);
    __nv_bfloat16 hy = __float2bfloat16(y);
    float rx = x - __bfloat162float(hx);
    float ry = y - __bfloat162float(hy);
    __nv_bfloat16 lx = __float2bfloat16(rx);
    __nv_bfloat16 ly = __float2bfloat16(ry);
    hp = (uint32_t)__bfloat16_as_ushort(hx) | ((uint32_t)__bfloat16_as_ushort(hy) << 16);
    lp = (uint32_t)__bfloat16_as_ushort(lx) | ((uint32_t)__bfloat16_as_ushort(ly) << 16);
}

#define LDMX4(r0,r1,r2,r3,addr) \
    asm volatile("ldmatrix.sync.aligned.m8n8.x4.shared.b16 {%0,%1,%2,%3}, [%4];" \
                 : "=r"(r0), "=r"(r1), "=r"(r2), "=r"(r3) : "r"(addr))

#define LDMX4T(r0,r1,r2,r3,addr) \
    asm volatile("ldmatrix.sync.aligned.m8n8.x4.trans.shared.b16 {%0,%1,%2,%3}, [%4];" \
                 : "=r"(r0), "=r"(r1), "=r"(r2), "=r"(r3) : "r"(addr))

#define MMA16816(c, a, b) \
    asm volatile("mma.sync.aligned.m16n8k16.row.col.f32.bf16.bf16.f32 " \
                 "{%0,%1,%2,%3}, {%4,%5,%6,%7}, {%8,%9}, {%0,%1,%2,%3};" \
                 : "+f"((c)[0]), "+f"((c)[1]), "+f"((c)[2]), "+f"((c)[3]) \
                 : "r"((a)[0]), "r"((a)[1]), "r"((a)[2]), "r"((a)[3]), \
                   "r"((b)[0]), "r"((b)[1]))

// ---------------------------------------------------------------- rmsnorm --
__global__ void rmsnorm_kernel(const float* __restrict__ x,
                               const float* __restrict__ w,
                               float* __restrict__ out)
{
    const int row = blockIdx.x;
    const float* xr = x + (size_t)row * D_;
    float ss = 0.f;
    for (int i = threadIdx.x; i < D_; i += blockDim.x) {
        float v = xr[i];
        ss += v * v;
    }
    __shared__ float red[32];
    #pragma unroll
    for (int o = 16; o; o >>= 1) ss += __shfl_xor_sync(0xffffffffu, ss, o);
    if ((threadIdx.x & 31) == 0) red[threadIdx.x >> 5] = ss;
    __syncthreads();
    if (threadIdx.x < 32) {
        float v = (threadIdx.x < (blockDim.x >> 5)) ? red[threadIdx.x] : 0.f;
        #pragma unroll
        for (int o = 16; o; o >>= 1) v += __shfl_xor_sync(0xffffffffu, v, o);
        if (threadIdx.x == 0) red[0] = v;
    }
    __syncthreads();
    const float n   = sqrtf(red[0]) * rsqrtf((float)D_);
    const float inv = 1.f / (n + EPS_);
    float* orow = out + (size_t)row * D_;
    for (int i = threadIdx.x; i < D_; i += blockDim.x)
        orow[i] = xr[i] * inv * w[i];
}

// --------------------------------------------------------------- mma gemm --
// C[M,N] = A[M,K] @ B[K,N] + bias; EPI: 0=bias, 1=bias+SiLU, 2=bias+residual
// bf16 3-term split (hi+lo) on tensor cores, fp32 accumulate.
// 128x128x32 tiles, 8 warps (2x4), 64x32 warp tile, m16n8k16.
//
// A smem: [128 rows][32 k] bf16, 64B rows, 16B chunks XOR-swizzled:
//   physical chunk p = (k/8) ^ ((row>>1)&3)  -> ldmatrix conflict-free.
// B smem: [32 k rows][128+8 n] bf16 (272B rows) -> ldmatrix.trans conflict-free.
template<int EPI>
__global__ void __launch_bounds__(256)
mma_gemm_kernel(const float* __restrict__ A, const float* __restrict__ Bm,
                const float* __restrict__ bias, const float* __restrict__ res,
                float* __restrict__ C, int M, int N, int K)
{
    __shared__ __align__(16) __nv_bfloat16 Ahi[128 * 32];
    __shared__ __align__(16) __nv_bfloat16 Alo[128 * 32];
    __shared__ __align__(16) __nv_bfloat16 Bhi[32 * 136];
    __shared__ __align__(16) __nv_bfloat16 Blo[32 * 136];

    const int tid  = threadIdx.x;
    const int lane = tid & 31;
    const int warp = tid >> 5;
    const int wm   = (warp >> 2) * 64;   // warp row offset in tile
    const int wn   = (warp & 3) * 32;    // warp col offset in tile
    const int bm   = blockIdx.y * 128;
    const int bn   = blockIdx.x * 128;

    float acc[4][4][4];
    #pragma unroll
    for (int i = 0; i < 4; i++)
        #pragma unroll
        for (int j = 0; j < 4; j++)
            #pragma unroll
            for (int r = 0; r < 4; r++) acc[i][j][r] = 0.f;

    // global-load mapping:
    // A: idx = tid + i*256 -> r = idx>>3 (0..127), kc = (idx&7)*4
    // B: idx = tid + i*256 -> r = idx>>5 (0..31),  c  = (idx&31)*4
    float4 av[4], bv[4];
    #pragma unroll
    for (int i = 0; i < 4; i++) {
        int idx = tid + i * 256;
        int r = idx >> 3, kc = (idx & 7) << 2;
        av[i] = *(const float4*)(A + (size_t)(bm + r) * K + kc);
        int rb = idx >> 5, c = (idx & 31) << 2;
        bv[i] = *(const float4*)(Bm + (size_t)rb * N + bn + c);
    }

    for (int k0 = 0; k0 < K; k0 += 32) {
        // ---- stage current tile into smem (convert fp32 -> bf16 hi/lo) ----
        #pragma unroll
        for (int i = 0; i < 4; i++) {
            int idx = tid + i * 256;
            // A
            {
                int r = idx >> 3, kc = (idx & 7) << 2;
                uint32_t h0, l0, h1, l1;
                split2(av[i].x, av[i].y, h0, l0);
                split2(av[i].z, av[i].w, h1, l1);
                int p = (kc >> 3) ^ ((r >> 1) & 3);
                int off = r * 64 + p * 16 + ((kc & 4) << 1);
                *(uint2*)((char*)Ahi + off) = make_uint2(h0, h1);
                *(uint2*)((char*)Alo + off) = make_uint2(l0, l1);
            }
            // B
            {
                int r = idx >> 5, c = (idx & 31) << 2;
                uint32_t h0, l0, h1, l1;
                split2(bv[i].x, bv[i].y, h0, l0);
                split2(bv[i].z, bv[i].w, h1, l1);
                int off = r * 272 + c * 2;
                *(uint2*)((char*)Bhi + off) = make_uint2(h0, h1);
                *(uint2*)((char*)Blo + off) = make_uint2(l0, l1);
            }
        }
        __syncthreads();

        // ---- prefetch next tile to registers (hidden behind MMA work) ----
        if (k0 + 32 < K) {
            #pragma unroll
            for (int i = 0; i < 4; i++) {
                int idx = tid + i * 256;
                int r = idx >> 3, kc = (idx & 7) << 2;
                av[i] = *(const float4*)(A + (size_t)(bm + r) * K + (k0 + 32) + kc);
                int rb = idx >> 5, c = (idx & 31) << 2;
                bv[i] = *(const float4*)(Bm + (size_t)(k0 + 32 + rb) * N + bn + c);
            }
        }

        // ---- MMA over the tile: 2 k-steps of 16 ----
        #pragma unroll
        for (int ks = 0; ks < 2; ks++) {
            uint32_t bh[4][2], bl[4][2];
            #pragma unroll
            for (int half = 0; half < 2; half++) {
                int krow = ks * 16 + (lane & 15);
                int ncol = wn + half * 16 + ((lane >> 4) << 3);
                int off  = krow * 272 + ncol * 2;
                LDMX4T(bh[half*2][0], bh[half*2][1], bh[half*2+1][0], bh[half*2+1][1],
                       sptr((char*)Bhi + off));
                LDMX4T(bl[half*2][0], bl[half*2][1], bl[half*2+1][0], bl[half*2+1][1],
                       sptr((char*)Blo + off));
            }
            #pragma unroll
            for (int mi = 0; mi < 4; mi++) {
                int r  = wm + mi * 16 + (lane & 15);
                int cl = ks * 2 + (lane >> 4);
                int p  = cl ^ ((r >> 1) & 3);
                int off = r * 64 + p * 16;
                uint32_t ah[4], al[4];
                LDMX4(ah[0], ah[1], ah[2], ah[3], sptr((char*)Ahi + off));
                LDMX4(al[0], al[1], al[2], al[3], sptr((char*)Alo + off));
                #pragma unroll
                for (int nj = 0; nj < 4; nj++) {
                    MMA16816(acc[mi][nj], al, bh[nj]);   // lo*hi
                    MMA16816(acc[mi][nj], ah, bl[nj]);   // hi*lo
                    MMA16816(acc[mi][nj], ah, bh[nj]);   // hi*hi
                }
            }
        }
        __syncthreads();
    }

    // ---- epilogue ----
    const int g = lane >> 2, t = lane & 3;
    #pragma unroll
    for (int mi = 0; mi < 4; mi++) {
        #pragma unroll
        for (int nj = 0; nj < 4; nj++) {
            int col = bn + wn + nj * 8 + t * 2;
            float b0 = bias[col], b1 = bias[col + 1];
            #pragma unroll
            for (int half = 0; half < 2; half++) {
                size_t row = (size_t)(bm + wm + mi * 16 + g + half * 8);
                float v0 = acc[mi][nj][half * 2 + 0] + b0;
                float v1 = acc[mi][nj][half * 2 + 1] + b1;
                if (EPI == 1) {
                    v0 = v0 / (1.f + expf(-v0));
                    v1 = v1 / (1.f + expf(-v1));
                }
                if (EPI == 2) {
                    const float2 rv = *(const float2*)(res + row * (size_t)N + col);
                    v0 += rv.x; v1 += rv.y;
                }
                float2 o = make_float2(v0, v1);
                *(float2*)(C + row * (size_t)N + col) = o;
            }
        }
    }
}

// ------------------------------------------------------------------- rope --
__global__ void rope_kernel(float* __restrict__ qkv)
{
    const int half = HD_ / 2;                    // 64
    const int per  = NT_ * H_ * half;            // elements per (q|k)
    int idx = blockIdx.x * blockDim.x + threadIdx.x;
    if (idx >= 2 * per) return;
    const int which = idx / per;                 // 0 = q, 1 = k
    int rem   = idx - which * per;
    const int tok = rem / (H_ * half);
    const int hh  = (rem / half) % H_;
    const int d   = rem % half;
    const int t   = tok % T_;

    double rate  = pow(10000.0, -2.0 * (double)d / (double)HD_);
    double theta = (double)t * rate;
    double sd, cd;
    sincos(theta, &sd, &cd);
    const float s = (float)sd, c = (float)cd;

    float* base = qkv + (size_t)tok * (3 * D_) + (size_t)which * D_ + hh * HD_;
    float x1v = base[d];
    float x2v = base[d + half];
    base[d]        = x1v * c - x2v * s;
    base[d + half] = x1v * s + x2v * c;
}

// -------------------------------------------------------- flash attention --
#define PT_STRIDE 68
#define ATTN_SMEM ((128*64 + 128*64 + 64*128 + 64*PT_STRIDE) * 4)

__global__ void __launch_bounds__(128)
attn_kernel(const float* __restrict__ qkv, float* __restrict__ y)
{
    extern __shared__ float sm[];
    float* Qs = sm;                      // [128][64]
    float* Ks = sm + 128 * 64;           // [128][64]
    float* Vs = Ks + 128 * 64;           // [64][128]
    float* Pt = Vs + 64 * 128;           // [64][PT_STRIDE]

    const int qb  = blockIdx.x;
    const int bh  = blockIdx.y;
    const int b   = bh >> 4;
    const int h   = bh & 15;
    const int tid = threadIdx.x;
    const int ty  = tid >> 3;
    const int tx  = tid & 7;

    const size_t rs = 3 * D_;
    const float* qbase = qkv + ((size_t)(b * T_ + qb * 64)) * rs + h * HD_;

    #pragma unroll
    for (int it = 0; it < 16; it++) {
        int idx = tid + it * 128;
        int r   = idx >> 5;
        int d4  = (idx & 31) << 2;
        float4 v = *(const float4*)(qbase + (size_t)r * rs + d4);
        Qs[(d4 + 0) * 64 + r] = v.x;
        Qs[(d4 + 1) * 64 + r] = v.y;
        Qs[(d4 + 2) * 64 + r] = v.z;
        Qs[(d4 + 3) * 64 + r] = v.w;
    }

    float o[4][16];
    #pragma unroll
    for (int i = 0; i < 4; i++)
        #pragma unroll
        for (int j = 0; j < 16; j++) o[i][j] = 0.f;
    float m[4], l[4];
    #pragma unroll
    for (int i = 0; i < 4; i++) { m[i] = -1e30f; l[i] = 0.f; }

    const float scale = 0.08838834764831843f;

    for (int kb = 0; kb <= qb; kb++) {
        __syncthreads();
        const float* kbase = qkv + ((size_t)(b * T_ + kb * 64)) * rs + D_ + h * HD_;
        const float* vbase = kbase + D_;
        #pragma unroll
        for (int it = 0; it < 16; it++) {
            int idx = tid + it * 128;
            int r   = idx >> 5;
            int d4  = (idx & 31) << 2;
            float4 kv = *(const float4*)(kbase + (size_t)r * rs + d4);
            Ks[(d4 + 0) * 64 + r] = kv.x;
            Ks[(d4 + 1) * 64 + r] = kv.y;
            Ks[(d4 + 2) * 64 + r] = kv.z;
            Ks[(d4 + 3) * 64 + r] = kv.w;
            float4 vv = *(const float4*)(vbase + (size_t)r * rs + d4);
            *(float4*)&Vs[r * 128 + d4] = vv;
        }
        __syncthreads();

        float s[4][8];
        #pragma unroll
        for (int i = 0; i < 4; i++)
            #pragma unroll
            for (int j = 0; j < 8; j++) s[i][j] = 0.f;
        #pragma unroll 4
        for (int kk = 0; kk < 128; kk++) {
            float4 qa = *(const float4*)&Qs[kk * 64 + ty * 4];
            float4 ka = *(const float4*)&Ks[kk * 64 + tx * 4];
            float4 kh = *(const float4*)&Ks[kk * 64 + 32 + tx * 4];
            float qv[4] = {qa.x, qa.y, qa.z, qa.w};
            float kv8[8] = {ka.x, ka.y, ka.z, ka.w, kh.x, kh.y, kh.z, kh.w};
            #pragma unroll
            for (int i = 0; i < 4; i++)
                #pragma unroll
                for (int j = 0; j < 8; j++)
                    s[i][j] = fmaf(qv[i], kv8[j], s[i][j]);
        }

        const bool diag = (kb == qb);
        #pragma unroll
        for (int i = 0; i < 4; i++) {
            int rloc = ty * 4 + i;
            #pragma unroll
            for (int j = 0; j < 8; j++) {
                float v = s[i][j] * scale;
                if (diag) {
                    int c = (j < 4) ? (tx * 4 + j) : (32 + tx * 4 + (j - 4));
                    if (c > rloc) v = -1e30f;
                }
                s[i][j] = v;
            }
        }

        #pragma unroll
        for (int i = 0; i < 4; i++) {
            float rm = s[i][0];
            #pragma unroll
            for (int j = 1; j < 8; j++) rm = fmaxf(rm, s[i][j]);
            rm = fmaxf(rm, __shfl_xor_sync(0xffffffffu, rm, 1));
            rm = fmaxf(rm, __shfl_xor_sync(0xffffffffu, rm, 2));
            rm = fmaxf(rm, __shfl_xor_sync(0xffffffffu, rm, 4));
            float mn   = fmaxf(m[i], rm);
            float corr = expf(m[i] - mn);
            float rsum = 0.f;
            #pragma unroll
            for (int j = 0; j < 8; j++) {
                float p = expf(s[i][j] - mn);
                s[i][j] = p;
                rsum += p;
            }
            rsum += __shfl_xor_sync(0xffffffffu, rsum, 1);
            rsum += __shfl_xor_sync(0xffffffffu, rsum, 2);
            rsum += __shfl_xor_sync(0xffffffffu, rsum, 4);
            l[i] = l[i] * corr + rsum;
            m[i] = mn;
            #pragma unroll
            for (int j = 0; j < 16; j++) o[i][j] *= corr;
        }

        #pragma unroll
        for (int j = 0; j < 8; j++) {
            int c = (j < 4) ? (tx * 4 + j) : (32 + tx * 4 + (j - 4));
            float4 pv = make_float4(s[0][j], s[1][j], s[2][j], s[3][j]);
            *(float4*)&Pt[c * PT_STRIDE + ty * 4] = pv;
        }
        __syncthreads();

        #pragma unroll 2
        for (int j = 0; j < 64; j++) {
            float4 p4 = *(const float4*)&Pt[j * PT_STRIDE + ty * 4];
            float pv[4] = {p4.x, p4.y, p4.z, p4.w};
            #pragma unroll
            for (int jj = 0; jj < 4; jj++) {
                float4 v4 = *(const float4*)&Vs[j * 128 + jj * 32 + tx * 4];
                float vv[4] = {v4.x, v4.y, v4.z, v4.w};
                #pragma unroll
                for (int i = 0; i < 4; i++)
                    #pragma unroll
                    for (int cc = 0; cc < 4; cc++)
                        o[i][jj * 4 + cc] = fmaf(pv[i], vv[cc], o[i][jj * 4 + cc]);
            }
        }
    }

    #pragma unroll
    for (int i = 0; i < 4; i++) {
        float invl = 1.f / l[i];
        size_t row = (size_t)(b * T_ + qb * 64 + ty * 4 + i);
        float* yrow = y + row * D_ + h * HD_;
        #pragma unroll
        for (int jj = 0; jj < 4; jj++) {
            float4 v;
            v.x = o[i][jj * 4 + 0] * invl;
            v.y = o[i][jj * 4 + 1] * invl;
            v.z = o[i][jj * 4 + 2] * invl;
            v.w = o[i][jj * 4 + 3] * invl;
            *(float4*)(yrow + jj * 32 + tx * 4) = v;
        }
    }
}

// ------------------------------------------------------------------- host --
extern "C" void kernel_launch(void* const* d_in, const int* in_sizes, int n_in,
                              void* d_out, int out_size)
{
    const float* x       = (const float*)d_in[0];
    const float* w_norm1 = (const float*)d_in[2];
    const float* w_qkv   = (const float*)d_in[3];
    const float* b_qkv   = (const float*)d_in[4];
    const float* w_proj  = (const float*)d_in[5];
    const float* b_proj  = (const float*)d_in[6];
    const float* w_norm2 = (const float*)d_in[7];
    const float* w_fc1   = (const float*)d_in[8];
    const float* b_fc1   = (const float*)d_in[9];
    const float* w_fc2   = (const float*)d_in[10];
    const float* b_fc2   = (const float*)d_in[11];
    float* out = (float*)d_out;

    float *h, *qkv, *y, *x1, *h2;
    cudaGetSymbolAddress((void**)&h,   g_h);
    cudaGetSymbolAddress((void**)&qkv, g_qkv);
    cudaGetSymbolAddress((void**)&y,   g_y);
    cudaGetSymbolAddress((void**)&x1,  g_x1);
    cudaGetSymbolAddress((void**)&h2,  g_h2);

    cudaFuncSetAttribute(attn_kernel,
                         cudaFuncAttributeMaxDynamicSharedMemorySize, ATTN_SMEM);

    // 1. h = rmsnorm(x, w_norm1)
    rmsnorm_kernel<<<NT_, 256>>>(x, w_norm1, h);
    // 2. qkv = h @ w_qkv + b_qkv
    mma_gemm_kernel<0><<<dim3(3 * D_ / 128, NT_ / 128), 256>>>(
        h, w_qkv, b_qkv, nullptr, qkv, NT_, 3 * D_, D_);
    // 3. rope(q, k) in place
    rope_kernel<<<(2 * NT_ * H_ * (HD_ / 2)) / 256, 256>>>(qkv);
    // 4. y = causal attention
    attn_kernel<<<dim3(T_ / 64, B_ * H_), 128, ATTN_SMEM>>>(qkv, y);
    // 5. x1 = x + (y @ w_proj + b_proj)
    mma_gemm_kernel<2><<<dim3(D_ / 128, NT_ / 128), 256>>>(
        y, w_proj, b_proj, x, x1, NT_, D_, D_);
    // 6. h = rmsnorm(x1, w_norm2)
    rmsnorm_kernel<<<NT_, 256>>>(x1, w_norm2, h);
    // 7. h2 = silu(h @ w_fc1 + b_fc1)
    mma_gemm_kernel<1><<<dim3(4 * D_ / 128, NT_ / 128), 256>>>(
        h, w_fc1, b_fc1, nullptr, h2, NT_, 4 * D_, D_);
    // 8. out = x1 + (h2 @ w_fc2 + b_fc2)
    mma_gemm_kernel<2><<<dim3(D_ / 128, NT_ / 128), 256>>>(
        h2, w_fc2, b_fc2, x1, out, NT_, D_, 4 * D_);
}

// round 8
// speedup vs baseline: 1.7534x; 1.1676x over previous
#include <cuda_runtime.h>
#include <cuda_bf16.h>
#include <math.h>
#include <stdint.h>

#define D_   2048
#define H_   16
#define HD_  128
#define B_   2
#define T_   2048
#define NT_  (B_*T_)          // 4096 tokens
#define EPS_ 1e-6f

// ---------------- scratch (static device arrays; no allocation allowed) ----
__device__ float g_h  [(size_t)NT_ * D_];        // 32 MB  rmsnorm output
__device__ float g_qkv[(size_t)NT_ * 3 * D_];    // 96 MB  qkv (rope applied in place)
__device__ float g_y  [(size_t)NT_ * D_];        // 32 MB  attention output
__device__ float g_x1 [(size_t)NT_ * D_];        // 32 MB  x + attn proj
__device__ float g_h2 [(size_t)NT_ * 4 * D_];    // 128 MB fc1 output

// ---------------------------------------------------------------- helpers --
__device__ __forceinline__ uint32_t sptr(const void* p) {
    return (uint32_t)__cvta_generic_to_shared(p);
}

// split two fp32 into packed bf16 hi / lo pairs (lo = residual)
__device__ __forceinline__ void split2(float x, float y, uint32_t& hp, uint32_t& lp) {
    __nv_bfloat16 hx = __float2bfloat16(x);
    __nv_bfloat16 hy = __float2bfloat16(y);
    float rx = x - __bfloat162float(hx);
    float ry = y - __bfloat162float(hy);
    __nv_bfloat16 lx = __float2bfloat16(rx);
    __nv_bfloat16 ly = __float2bfloat16(ry);
    hp = (uint32_t)__bfloat16_as_ushort(hx) | ((uint32_t)__bfloat16_as_ushort(hy) << 16);
    lp = (uint32_t)__bfloat16_as_ushort(lx) | ((uint32_t)__bfloat16_as_ushort(ly) << 16);
}

#define LDMX4(r0,r1,r2,r3,addr) \
    asm volatile("ldmatrix.sync.aligned.m8n8.x4.shared.b16 {%0,%1,%2,%3}, [%4];" \
                 : "=r"(r0), "=r"(r1), "=r"(r2), "=r"(r3) : "r"(addr))

#define LDMX4T(r0,r1,r2,r3,addr) \
    asm volatile("ldmatrix.sync.aligned.m8n8.x4.trans.shared.b16 {%0,%1,%2,%3}, [%4];" \
                 : "=r"(r0), "=r"(r1), "=r"(r2), "=r"(r3) : "r"(addr))

#define MMA16816(c, a, b) \
    asm volatile("mma.sync.aligned.m16n8k16.row.col.f32.bf16.bf16.f32 " \
                 "{%0,%1,%2,%3}, {%4,%5,%6,%7}, {%8,%9}, {%0,%1,%2,%3};" \
                 : "+f"((c)[0]), "+f"((c)[1]), "+f"((c)[2]), "+f"((c)[3]) \
                 : "r"((a)[0]), "r"((a)[1]), "r"((a)[2]), "r"((a)[3]), \
                   "r"((b)[0]), "r"((b)[1]))

// ---------------------------------------------------------------- rmsnorm --
__global__ void rmsnorm_kernel(const float* __restrict__ x,
                               const float* __restrict__ w,
                               float* __restrict__ out)
{
    const int row = blockIdx.x;
    const float* xr = x + (size_t)row * D_;
    float ss = 0.f;
    for (int i = threadIdx.x; i < D_; i += blockDim.x) {
        float v = xr[i];
        ss += v * v;
    }
    __shared__ float red[32];
    #pragma unroll
    for (int o = 16; o; o >>= 1) ss += __shfl_xor_sync(0xffffffffu, ss, o);
    if ((threadIdx.x & 31) == 0) red[threadIdx.x >> 5] = ss;
    __syncthreads();
    if (threadIdx.x < 32) {
        float v = (threadIdx.x < (blockDim.x >> 5)) ? red[threadIdx.x] : 0.f;
        #pragma unroll
        for (int o = 16; o; o >>= 1) v += __shfl_xor_sync(0xffffffffu, v, o);
        if (threadIdx.x == 0) red[0] = v;
    }
    __syncthreads();
    const float n   = sqrtf(red[0]) * rsqrtf((float)D_);
    const float inv = 1.f / (n + EPS_);
    float* orow = out + (size_t)row * D_;
    for (int i = threadIdx.x; i < D_; i += blockDim.x)
        orow[i] = xr[i] * inv * w[i];
}

// --------------------------------------------------------------- mma gemm --
// (unchanged from round 7 — validated) bf16 3-term split tensor-core GEMM.
template<int EPI>
__global__ void __launch_bounds__(256)
mma_gemm_kernel(const float* __restrict__ A, const float* __restrict__ Bm,
                const float* __restrict__ bias, const float* __restrict__ res,
                float* __restrict__ C, int M, int N, int K)
{
    __shared__ __align__(16) __nv_bfloat16 Ahi[128 * 32];
    __shared__ __align__(16) __nv_bfloat16 Alo[128 * 32];
    __shared__ __align__(16) __nv_bfloat16 Bhi[32 * 136];
    __shared__ __align__(16) __nv_bfloat16 Blo[32 * 136];

    const int tid  = threadIdx.x;
    const int lane = tid & 31;
    const int warp = tid >> 5;
    const int wm   = (warp >> 2) * 64;
    const int wn   = (warp & 3) * 32;
    const int bm   = blockIdx.y * 128;
    const int bn   = blockIdx.x * 128;

    float acc[4][4][4];
    #pragma unroll
    for (int i = 0; i < 4; i++)
        #pragma unroll
        for (int j = 0; j < 4; j++)
            #pragma unroll
            for (int r = 0; r < 4; r++) acc[i][j][r] = 0.f;

    float4 av[4], bv[4];
    #pragma unroll
    for (int i = 0; i < 4; i++) {
        int idx = tid + i * 256;
        int r = idx >> 3, kc = (idx & 7) << 2;
        av[i] = *(const float4*)(A + (size_t)(bm + r) * K + kc);
        int rb = idx >> 5, c = (idx & 31) << 2;
        bv[i] = *(const float4*)(Bm + (size_t)rb * N + bn + c);
    }

    for (int k0 = 0; k0 < K; k0 += 32) {
        #pragma unroll
        for (int i = 0; i < 4; i++) {
            int idx = tid + i * 256;
            {
                int r = idx >> 3, kc = (idx & 7) << 2;
                uint32_t h0, l0, h1, l1;
                split2(av[i].x, av[i].y, h0, l0);
                split2(av[i].z, av[i].w, h1, l1);
                int p = (kc >> 3) ^ ((r >> 1) & 3);
                int off = r * 64 + p * 16 + ((kc & 4) << 1);
                *(uint2*)((char*)Ahi + off) = make_uint2(h0, h1);
                *(uint2*)((char*)Alo + off) = make_uint2(l0, l1);
            }
            {
                int r = idx >> 5, c = (idx & 31) << 2;
                uint32_t h0, l0, h1, l1;
                split2(bv[i].x, bv[i].y, h0, l0);
                split2(bv[i].z, bv[i].w, h1, l1);
                int off = r * 272 + c * 2;
                *(uint2*)((char*)Bhi + off) = make_uint2(h0, h1);
                *(uint2*)((char*)Blo + off) = make_uint2(l0, l1);
            }
        }
        __syncthreads();

        if (k0 + 32 < K) {
            #pragma unroll
            for (int i = 0; i < 4; i++) {
                int idx = tid + i * 256;
                int r = idx >> 3, kc = (idx & 7) << 2;
                av[i] = *(const float4*)(A + (size_t)(bm + r) * K + (k0 + 32) + kc);
                int rb = idx >> 5, c = (idx & 31) << 2;
                bv[i] = *(const float4*)(Bm + (size_t)(k0 + 32 + rb) * N + bn + c);
            }
        }

        #pragma unroll
        for (int ks = 0; ks < 2; ks++) {
            uint32_t bh[4][2], bl[4][2];
            #pragma unroll
            for (int half = 0; half < 2; half++) {
                int krow = ks * 16 + (lane & 15);
                int ncol = wn + half * 16 + ((lane >> 4) << 3);
                int off  = krow * 272 + ncol * 2;
                LDMX4T(bh[half*2][0], bh[half*2][1], bh[half*2+1][0], bh[half*2+1][1],
                       sptr((char*)Bhi + off));
                LDMX4T(bl[half*2][0], bl[half*2][1], bl[half*2+1][0], bl[half*2+1][1],
                       sptr((char*)Blo + off));
            }
            #pragma unroll
            for (int mi = 0; mi < 4; mi++) {
                int r  = wm + mi * 16 + (lane & 15);
                int cl = ks * 2 + (lane >> 4);
                int p  = cl ^ ((r >> 1) & 3);
                int off = r * 64 + p * 16;
                uint32_t ah[4], al[4];
                LDMX4(ah[0], ah[1], ah[2], ah[3], sptr((char*)Ahi + off));
                LDMX4(al[0], al[1], al[2], al[3], sptr((char*)Alo + off));
                #pragma unroll
                for (int nj = 0; nj < 4; nj++) {
                    MMA16816(acc[mi][nj], al, bh[nj]);
                    MMA16816(acc[mi][nj], ah, bl[nj]);
                    MMA16816(acc[mi][nj], ah, bh[nj]);
                }
            }
        }
        __syncthreads();
    }

    const int g = lane >> 2, t = lane & 3;
    #pragma unroll
    for (int mi = 0; mi < 4; mi++) {
        #pragma unroll
        for (int nj = 0; nj < 4; nj++) {
            int col = bn + wn + nj * 8 + t * 2;
            float b0 = bias[col], b1 = bias[col + 1];
            #pragma unroll
            for (int half = 0; half < 2; half++) {
                size_t row = (size_t)(bm + wm + mi * 16 + g + half * 8);
                float v0 = acc[mi][nj][half * 2 + 0] + b0;
                float v1 = acc[mi][nj][half * 2 + 1] + b1;
                if (EPI == 1) {
                    v0 = v0 / (1.f + expf(-v0));
                    v1 = v1 / (1.f + expf(-v1));
                }
                if (EPI == 2) {
                    const float2 rv = *(const float2*)(res + row * (size_t)N + col);
                    v0 += rv.x; v1 += rv.y;
                }
                float2 o = make_float2(v0, v1);
                *(float2*)(C + row * (size_t)N + col) = o;
            }
        }
    }
}

// ------------------------------------------------------------------- rope --
__global__ void rope_kernel(float* __restrict__ qkv)
{
    const int half = HD_ / 2;                    // 64
    const int per  = NT_ * H_ * half;            // elements per (q|k)
    int idx = blockIdx.x * blockDim.x + threadIdx.x;
    if (idx >= 2 * per) return;
    const int which = idx / per;                 // 0 = q, 1 = k
    int rem   = idx - which * per;
    const int tok = rem / (H_ * half);
    const int hh  = (rem / half) % H_;
    const int d   = rem % half;
    const int t   = tok % T_;

    double rate  = pow(10000.0, -2.0 * (double)d / (double)HD_);
    double theta = (double)t * rate;
    double sd, cd;
    sincos(theta, &sd, &cd);
    const float s = (float)sd, c = (float)cd;

    float* base = qkv + (size_t)tok * (3 * D_) + (size_t)which * D_ + hh * HD_;
    float x1v = base[d];
    float x2v = base[d + half];
    base[d]        = x1v * c - x2v * s;
    base[d + half] = x1v * s + x2v * c;
}

// ---------------------------------------- tensor-core flash attention -----
// BQ=128 q rows per CTA, BK=64 kv per tile, 8 warps (each m16), HD=128.
// bf16 3-term split for QK^T and PV; fp32 online softmax in registers.
//
// Smem layouts (all bf16, hi+lo copies):
//  Q,K: [rows][128] with 256B rows, 16B chunks swizzled: phys=(c&8)|((c&7)^(r&7))
//       -> non-trans ldmatrix conflict-free (Q as A-operand, K as B-operand).
//  V:   [64 kv rows][128+8] (272B stride) -> ldmatrix.trans B-operand
//       (identical to validated GEMM B layout).
#define QHI_OFF 0
#define QLO_OFF (128*256)
#define KHI_OFF (2*128*256)
#define KLO_OFF (2*128*256 + 64*256)
#define VHI_OFF (2*128*256 + 2*64*256)
#define VLO_OFF (2*128*256 + 2*64*256 + 64*272)
#define ATTN_SMEM (2*128*256 + 2*64*256 + 2*64*272)   // 133120 bytes

__global__ void __launch_bounds__(256, 1)
attn_mma_kernel(const float* __restrict__ qkv, float* __restrict__ y)
{
    extern __shared__ char smx[];

    const int qb   = (T_ / 128 - 1) - blockIdx.x;   // heavy blocks first
    const int bh   = blockIdx.y;
    const int b    = bh >> 4;
    const int h    = bh & 15;
    const int tid  = threadIdx.x;
    const int lane = tid & 31;
    const int warp = tid >> 5;
    const int g    = lane >> 2;      // row in group
    const int itg  = lane & 3;
    const size_t rs = 3 * D_;

    // ---- stage Q (pre-scaled) into smem hi/lo ----
    const float scale = 0.08838834764831843f;   // HD^-0.5
    const float* qgbase = qkv + (size_t)(b * T_ + qb * 128) * rs + h * HD_;
    #pragma unroll
    for (int i = 0; i < 16; i++) {
        int idx = tid + i * 256;
        int r   = idx >> 5;              // 0..127
        int c4  = (idx & 31) << 2;       // 0..124
        float4 v = *(const float4*)(qgbase + (size_t)r * rs + c4);
        v.x *= scale; v.y *= scale; v.z *= scale; v.w *= scale;
        uint32_t h0, l0, h1, l1;
        split2(v.x, v.y, h0, l0);
        split2(v.z, v.w, h1, l1);
        int c = c4 >> 3;
        int phys = (c & 8) | ((c & 7) ^ (r & 7));
        int off = r * 256 + phys * 16 + ((c4 & 4) << 1);
        *(uint2*)(smx + QHI_OFF + off) = make_uint2(h0, h1);
        *(uint2*)(smx + QLO_OFF + off) = make_uint2(l0, l1);
    }

    float o[16][4];
    #pragma unroll
    for (int i = 0; i < 16; i++)
        #pragma unroll
        for (int j = 0; j < 4; j++) o[i][j] = 0.f;
    float m[2] = {-1e30f, -1e30f};
    float l[2] = {0.f, 0.f};

    const int qbrow = qb * 128 + warp * 16;
    const int ntiles = 2 * qb + 2;

    for (int kb = 0; kb < ntiles; kb++) {
        __syncthreads();   // Q ready (1st iter) / K,V consumed (later iters)

        // ---- stage K, V tile into smem hi/lo ----
        const float* kgb = qkv + (size_t)(b * T_ + kb * 64) * rs + D_ + h * HD_;
        const float* vgb = kgb + D_;
        #pragma unroll
        for (int i = 0; i < 8; i++) {
            int idx = tid + i * 256;
            int r   = idx >> 5;              // 0..63
            int c4  = (idx & 31) << 2;       // 0..124
            float4 kv4 = *(const float4*)(kgb + (size_t)r * rs + c4);
            uint32_t h0, l0, h1, l1;
            split2(kv4.x, kv4.y, h0, l0);
            split2(kv4.z, kv4.w, h1, l1);
            int c = c4 >> 3;
            int phys = (c & 8) | ((c & 7) ^ (r & 7));
            int koff = r * 256 + phys * 16 + ((c4 & 4) << 1);
            *(uint2*)(smx + KHI_OFF + koff) = make_uint2(h0, h1);
            *(uint2*)(smx + KLO_OFF + koff) = make_uint2(l0, l1);

            float4 vv4 = *(const float4*)(vgb + (size_t)r * rs + c4);
            split2(vv4.x, vv4.y, h0, l0);
            split2(vv4.z, vv4.w, h1, l1);
            int voff = r * 272 + c4 * 2;
            *(uint2*)(smx + VHI_OFF + voff) = make_uint2(h0, h1);
            *(uint2*)(smx + VLO_OFF + voff) = make_uint2(l0, l1);
        }
        __syncthreads();

        // ---- S = Q @ K^T (3-term split) ----
        float s[8][4];
        #pragma unroll
        for (int i = 0; i < 8; i++)
            #pragma unroll
            for (int j = 0; j < 4; j++) s[i][j] = 0.f;

        #pragma unroll
        for (int ks = 0; ks < 8; ks++) {
            // Q A-fragments
            int qrow = warp * 16 + (lane & 15);
            int qc   = 2 * ks + (lane >> 4);
            int qph  = (qc & 8) | ((qc & 7) ^ (qrow & 7));
            uint32_t qoff = qrow * 256 + qph * 16;
            uint32_t qh[4], ql[4];
            LDMX4(qh[0], qh[1], qh[2], qh[3], sptr(smx + QHI_OFF + qoff));
            LDMX4(ql[0], ql[1], ql[2], ql[3], sptr(smx + QLO_OFF + qoff));

            // K B-fragments (row-major [kv][hd] == col-major kxn)
            uint32_t kbh[8][2], kbl[8][2];
            #pragma unroll
            for (int nb = 0; nb < 4; nb++) {
                int krow = nb * 16 + (lane & 7) + ((lane >> 4) << 3);
                int kc   = 2 * ks + ((lane >> 3) & 1);
                int kph  = (kc & 8) | ((kc & 7) ^ (krow & 7));
                uint32_t koff = krow * 256 + kph * 16;
                LDMX4(kbh[2*nb][0], kbh[2*nb][1], kbh[2*nb+1][0], kbh[2*nb+1][1],
                      sptr(smx + KHI_OFF + koff));
                LDMX4(kbl[2*nb][0], kbl[2*nb][1], kbl[2*nb+1][0], kbl[2*nb+1][1],
                      sptr(smx + KLO_OFF + koff));
            }
            #pragma unroll
            for (int nf = 0; nf < 8; nf++) {
                MMA16816(s[nf], ql, kbh[nf]);
                MMA16816(s[nf], qh, kbl[nf]);
                MMA16816(s[nf], qh, kbh[nf]);
            }
        }

        // ---- causal mask (only the two diagonal tiles need it) ----
        if (kb >= 2 * qb) {
            #pragma unroll
            for (int nf = 0; nf < 8; nf++)
                #pragma unroll
                for (int c = 0; c < 4; c++) {
                    int col = kb * 64 + nf * 8 + 2 * itg + (c & 1);
                    int row = qbrow + g + (c >> 1) * 8;
                    if (col > row) s[nf][c] = -1e30f;
                }
        }

        // ---- online softmax (rows g and g+8; stats shared across quad) ----
        #pragma unroll
        for (int rr = 0; rr < 2; rr++) {
            float rmax = -1e30f;
            #pragma unroll
            for (int nf = 0; nf < 8; nf++) {
                rmax = fmaxf(rmax, s[nf][rr*2]);
                rmax = fmaxf(rmax, s[nf][rr*2+1]);
            }
            rmax = fmaxf(rmax, __shfl_xor_sync(0xffffffffu, rmax, 1));
            rmax = fmaxf(rmax, __shfl_xor_sync(0xffffffffu, rmax, 2));
            float mn   = fmaxf(m[rr], rmax);
            float corr = __expf(m[rr] - mn);
            float rsum = 0.f;
            #pragma unroll
            for (int nf = 0; nf < 8; nf++) {
                float p0 = __expf(s[nf][rr*2]   - mn);
                float p1 = __expf(s[nf][rr*2+1] - mn);
                s[nf][rr*2]   = p0;
                s[nf][rr*2+1] = p1;
                rsum += p0 + p1;
            }
            rsum += __shfl_xor_sync(0xffffffffu, rsum, 1);
            rsum += __shfl_xor_sync(0xffffffffu, rsum, 2);
            l[rr] = l[rr] * corr + rsum;
            m[rr] = mn;
            #pragma unroll
            for (int nf = 0; nf < 16; nf++) {
                o[nf][rr*2]   *= corr;
                o[nf][rr*2+1] *= corr;
            }
        }

        // ---- O += P @ V (3-term split; P frags built in-register) ----
        #pragma unroll
        for (int sks = 0; sks < 4; sks++) {
            uint32_t pah[4], pal[4];
            split2(s[2*sks][0],   s[2*sks][1],   pah[0], pal[0]);
            split2(s[2*sks][2],   s[2*sks][3],   pah[1], pal[1]);
            split2(s[2*sks+1][0], s[2*sks+1][1], pah[2], pal[2]);
            split2(s[2*sks+1][2], s[2*sks+1][3], pah[3], pal[3]);
            #pragma unroll
            for (int nb = 0; nb < 8; nb++) {
                int vr = sks * 16 + (lane & 15);
                int vc = nb * 16 + ((lane >> 4) << 3);
                uint32_t voff = vr * 272 + vc * 2;
                uint32_t bh0[2], bh1[2], bl0[2], bl1[2];
                LDMX4T(bh0[0], bh0[1], bh1[0], bh1[1], sptr(smx + VHI_OFF + voff));
                LDMX4T(bl0[0], bl0[1], bl1[0], bl1[1], sptr(smx + VLO_OFF + voff));
                MMA16816(o[2*nb],   pal, bh0);
                MMA16816(o[2*nb],   pah, bl0);
                MMA16816(o[2*nb],   pah, bh0);
                MMA16816(o[2*nb+1], pal, bh1);
                MMA16816(o[2*nb+1], pah, bl1);
                MMA16816(o[2*nb+1], pah, bh1);
            }
        }
    }

    // ---- normalize + write y ----
    #pragma unroll
    for (int rr = 0; rr < 2; rr++) {
        float invl = 1.f / l[rr];
        size_t row = (size_t)(b * T_ + qbrow + g + rr * 8);
        float* yrow = y + row * D_ + h * HD_;
        #pragma unroll
        for (int nf = 0; nf < 16; nf++) {
            float2 v = make_float2(o[nf][rr*2] * invl, o[nf][rr*2+1] * invl);
            *(float2*)(yrow + nf * 8 + 2 * itg) = v;
        }
    }
}

// ------------------------------------------------------------------- host --
extern "C" void kernel_launch(void* const* d_in, const int* in_sizes, int n_in,
                              void* d_out, int out_size)
{
    const float* x       = (const float*)d_in[0];
    const float* w_norm1 = (const float*)d_in[2];
    const float* w_qkv   = (const float*)d_in[3];
    const float* b_qkv   = (const float*)d_in[4];
    const float* w_proj  = (const float*)d_in[5];
    const float* b_proj  = (const float*)d_in[6];
    const float* w_norm2 = (const float*)d_in[7];
    const float* w_fc1   = (const float*)d_in[8];
    const float* b_fc1   = (const float*)d_in[9];
    const float* w_fc2   = (const float*)d_in[10];
    const float* b_fc2   = (const float*)d_in[11];
    float* out = (float*)d_out;

    float *h, *qkv, *y, *x1, *h2;
    cudaGetSymbolAddress((void**)&h,   g_h);
    cudaGetSymbolAddress((void**)&qkv, g_qkv);
    cudaGetSymbolAddress((void**)&y,   g_y);
    cudaGetSymbolAddress((void**)&x1,  g_x1);
    cudaGetSymbolAddress((void**)&h2,  g_h2);

    cudaFuncSetAttribute(attn_mma_kernel,
                         cudaFuncAttributeMaxDynamicSharedMemorySize, ATTN_SMEM);

    // 1. h = rmsnorm(x, w_norm1)
    rmsnorm_kernel<<<NT_, 256>>>(x, w_norm1, h);
    // 2. qkv = h @ w_qkv + b_qkv
    mma_gemm_kernel<0><<<dim3(3 * D_ / 128, NT_ / 128), 256>>>(
        h, w_qkv, b_qkv, nullptr, qkv, NT_, 3 * D_, D_);
    // 3. rope(q, k) in place
    rope_kernel<<<(2 * NT_ * H_ * (HD_ / 2)) / 256, 256>>>(qkv);
    // 4. y = causal attention (tensor cores)
    attn_mma_kernel<<<dim3(T_ / 128, B_ * H_), 256, ATTN_SMEM>>>(qkv, y);
    // 5. x1 = x + (y @ w_proj + b_proj)
    mma_gemm_kernel<2><<<dim3(D_ / 128, NT_ / 128), 256>>>(
        y, w_proj, b_proj, x, x1, NT_, D_, D_);
    // 6. h = rmsnorm(x1, w_norm2)
    rmsnorm_kernel<<<NT_, 256>>>(x1, w_norm2, h);
    // 7. h2 = silu(h @ w_fc1 + b_fc1)
    mma_gemm_kernel<1><<<dim3(4 * D_ / 128, NT_ / 128), 256>>>(
        h, w_fc1, b_fc1, nullptr, h2, NT_, 4 * D_, D_);
    // 8. out = x1 + (h2 @ w_fc2 + b_fc2)
    mma_gemm_kernel<2><<<dim3(D_ / 128, NT_ / 128), 256>>>(
        h2, w_fc2, b_fc2, x1, out, NT_, D_, 4 * D_);
}

// round 13
// speedup vs baseline: 2.4137x; 1.3766x over previous
#include <cuda_runtime.h>
#include <cuda_bf16.h>
#include <math.h>
#include <stdint.h>

#define D_   2048
#define H_   16
#define HD_  128
#define B_   2
#define T_   2048
#define NT_  (B_*T_)          // 4096 tokens
#define EPS_ 1e-6f

// ---------------- scratch (static device arrays; no allocation allowed) ----
__device__ float g_qkv[(size_t)NT_ * 3 * D_];            // fp32 qkv (rope here)
__device__ float g_x1 [(size_t)NT_ * D_];                // fp32 x + proj
__device__ __nv_bfloat16 g_hhi [(size_t)NT_ * D_];       // rmsnorm out
__device__ __nv_bfloat16 g_hlo [(size_t)NT_ * D_];
__device__ __nv_bfloat16 g_yhi [(size_t)NT_ * D_];       // attention out
__device__ __nv_bfloat16 g_ylo [(size_t)NT_ * D_];
__device__ __nv_bfloat16 g_h2hi[(size_t)NT_ * 4 * D_];   // fc1 out
__device__ __nv_bfloat16 g_h2lo[(size_t)NT_ * 4 * D_];
__device__ __nv_bfloat16 g_qhi [(size_t)NT_ * D_];       // roped+scaled q
__device__ __nv_bfloat16 g_qlo [(size_t)NT_ * D_];
__device__ __nv_bfloat16 g_khi [(size_t)NT_ * D_];       // roped k
__device__ __nv_bfloat16 g_klo [(size_t)NT_ * D_];
__device__ __nv_bfloat16 g_vhi [(size_t)NT_ * D_];
__device__ __nv_bfloat16 g_vlo [(size_t)NT_ * D_];
// split weights, [K][N] bf16, concatenated
#define OFF_WQKV  0
#define OFF_WPROJ 12582912
#define OFF_WFC1  16777216
#define OFF_WFC2  33554432
#define WT_TOTAL  50331648
__device__ __nv_bfloat16 g_whi[WT_TOTAL];
__device__ __nv_bfloat16 g_wlo[WT_TOTAL];

// ---------------------------------------------------------------- helpers --
__device__ __forceinline__ uint32_t sptr(const void* p) {
    return (uint32_t)__cvta_generic_to_shared(p);
}

__device__ __forceinline__ void split2(float x, float y, uint32_t& hp, uint32_t& lp) {
    __nv_bfloat16 hx = __float2bfloat16(x);
    __nv_bfloat16 hy = __float2bfloat16(y);
    float rx = x - __bfloat162float(hx);
    float ry = y - __bfloat162float(hy);
    __nv_bfloat16 lx = __float2bfloat16(rx);
    __nv_bfloat16 ly = __float2bfloat16(ry);
    hp = (uint32_t)__bfloat16_as_ushort(hx) | ((uint32_t)__bfloat16_as_ushort(hy) << 16);
    lp = (uint32_t)__bfloat16_as_ushort(lx) | ((uint32_t)__bfloat16_as_ushort(ly) << 16);
}

#define LDMX4(r0,r1,r2,r3,addr) \
    asm volatile("ldmatrix.sync.aligned.m8n8.x4.shared.b16 {%0,%1,%2,%3}, [%4];" \
                 : "=r"(r0), "=r"(r1), "=r"(r2), "=r"(r3) : "r"(addr))

#define LDMX4T(r0,r1,r2,r3,addr) \
    asm volatile("ldmatrix.sync.aligned.m8n8.x4.trans.shared.b16 {%0,%1,%2,%3}, [%4];" \
                 : "=r"(r0), "=r"(r1), "=r"(r2), "=r"(r3) : "r"(addr))

#define MMA16816(c, a, b) \
    asm volatile("mma.sync.aligned.m16n8k16.row.col.f32.bf16.bf16.f32 " \
                 "{%0,%1,%2,%3}, {%4,%5,%6,%7}, {%8,%9}, {%0,%1,%2,%3};" \
                 : "+f"((c)[0]), "+f"((c)[1]), "+f"((c)[2]), "+f"((c)[3]) \
                 : "r"((a)[0]), "r"((a)[1]), "r"((a)[2]), "r"((a)[3]), \
                   "r"((b)[0]), "r"((b)[1]))

#define CPASYNC16(dst, src) \
    asm volatile("cp.async.cg.shared.global [%0], [%1], 16;" :: "r"(dst), "l"(src))
#define CPASYNC_COMMIT() asm volatile("cp.async.commit_group;" ::: "memory")
#define CPASYNC_WAIT0()  asm volatile("cp.async.wait_group 0;" ::: "memory")
#define CPASYNC_WAIT1()  asm volatile("cp.async.wait_group 1;" ::: "memory")

// ----------------------------------------------------------- weight split --
__global__ void wsplit_kernel(const float* __restrict__ w,
                              __nv_bfloat16* __restrict__ whi,
                              __nv_bfloat16* __restrict__ wlo, int npairs)
{
    int i = blockIdx.x * blockDim.x + threadIdx.x;
    if (i >= npairs) return;
    float2 v = ((const float2*)w)[i];
    uint32_t hp, lp;
    split2(v.x, v.y, hp, lp);
    ((uint32_t*)whi)[i] = hp;
    ((uint32_t*)wlo)[i] = lp;
}

// ---------------------------------------------------------- rmsnorm+split --
__global__ void rmsnorm_split_kernel(const float* __restrict__ x,
                                     const float* __restrict__ w,
                                     __nv_bfloat16* __restrict__ ohi,
                                     __nv_bfloat16* __restrict__ olo)
{
    const int row = blockIdx.x;
    const float2* xr = (const float2*)(x + (size_t)row * D_);
    const float2* w2 = (const float2*)w;
    float ss = 0.f;
    for (int i = threadIdx.x; i < D_ / 2; i += blockDim.x) {
        float2 v = xr[i];
        ss += v.x * v.x + v.y * v.y;
    }
    __shared__ float red[32];
    #pragma unroll
    for (int o = 16; o; o >>= 1) ss += __shfl_xor_sync(0xffffffffu, ss, o);
    if ((threadIdx.x & 31) == 0) red[threadIdx.x >> 5] = ss;
    __syncthreads();
    if (threadIdx.x < 32) {
        float v = (threadIdx.x < (blockDim.x >> 5)) ? red[threadIdx.x] : 0.f;
        #pragma unroll
        for (int o = 16; o; o >>= 1) v += __shfl_xor_sync(0xffffffffu, v, o);
        if (threadIdx.x == 0) red[0] = v;
    }
    __syncthreads();
    const float n   = sqrtf(red[0]) * rsqrtf((float)D_);
    const float inv = 1.f / (n + EPS_);
    uint32_t* oh = (uint32_t*)(ohi + (size_t)row * D_);
    uint32_t* ol = (uint32_t*)(olo + (size_t)row * D_);
    for (int i = threadIdx.x; i < D_ / 2; i += blockDim.x) {
        float2 v = xr[i];
        float2 ww = w2[i];
        uint32_t hp, lp;
        split2(v.x * inv * ww.x, v.y * inv * ww.y, hp, lp);
        oh[i] = hp;
        ol[i] = lp;
    }
}

// --------------------------------------------------------------- mma gemm --
// C[M,N] = A @ B + bias. A: [M][K] bf16 hi/lo. B: [K][N] bf16 hi/lo.
// EPI 0: fp32 C.  EPI 1: SiLU -> bf16 hi/lo.  EPI 2: +res -> fp32 C.
// 128x128x32 tiles, 8 warps, 64x32 warp tile, 3-term split, 2-stage cp.async.
// Per-stage smem: Ahi(8192) Alo(8192) Bhi(8704) Blo(8704) = 33792 B.
#define GS_ALO 8192
#define GS_BHI 16384
#define GS_BLO 25088
#define GS_STAGE 33792
#define GEMM_SMEM (2*GS_STAGE)

template<int EPI>
__global__ void __launch_bounds__(256)
mma_gemm_kernel(const __nv_bfloat16* __restrict__ Ah, const __nv_bfloat16* __restrict__ Al,
                const __nv_bfloat16* __restrict__ Bh, const __nv_bfloat16* __restrict__ Bl,
                const float* __restrict__ bias, const float* __restrict__ res,
                float* __restrict__ C,
                __nv_bfloat16* __restrict__ Chi, __nv_bfloat16* __restrict__ Clo,
                int M, int N, int K)
{
    extern __shared__ char sm[];
    const uint32_t smb = sptr(sm);
    const int tid  = threadIdx.x;
    const int lane = tid & 31;
    const int warp = tid >> 5;
    const int wm   = (warp >> 2) * 64;
    const int wn   = (warp & 3) * 32;
    const int bm   = blockIdx.y * 128;
    const int bn   = blockIdx.x * 128;

    float acc[4][4][4];
    #pragma unroll
    for (int i = 0; i < 4; i++)
        #pragma unroll
        for (int j = 0; j < 4; j++)
            #pragma unroll
            for (int r = 0; r < 4; r++) acc[i][j][r] = 0.f;

    const __nv_bfloat16* gAh = Ah + (size_t)bm * K;
    const __nv_bfloat16* gAl = Al + (size_t)bm * K;
    const __nv_bfloat16* gBh = Bh + bn;
    const __nv_bfloat16* gBl = Bl + bn;

    // stage k-chunk c into buffer (c&1)
    auto stage = [&](int c) {
        const uint32_t base = smb + (uint32_t)(c & 1) * GS_STAGE;
        const int k0 = c * 32;
        #pragma unroll
        for (int i = 0; i < 2; i++) {
            int idx = tid + i * 256;            // 0..511
            // A: r 0..127, ch 0..3 (8 bf16 each)
            int r  = idx >> 2, ch = idx & 3;
            int p  = ch ^ ((r >> 1) & 3);
            uint32_t ad = base + r * 64 + p * 16;
            size_t   as = (size_t)r * K + k0 + ch * 8;
            CPASYNC16(ad,          gAh + as);
            CPASYNC16(ad + GS_ALO, gAl + as);
            // B: kr 0..31, ch 0..15
            int kr = idx >> 4, bch = idx & 15;
            uint32_t bd = base + GS_BHI + kr * 272 + bch * 16;
            size_t   bs = (size_t)(k0 + kr) * N + bch * 8;
            CPASYNC16(bd,                    gBh + bs);
            CPASYNC16(bd + (GS_BLO-GS_BHI),  gBl + bs);
        }
        CPASYNC_COMMIT();
    };

    const int nchunk = K / 32;
    stage(0);

    for (int c = 0; c < nchunk; c++) {
        if (c + 1 < nchunk) { stage(c + 1); CPASYNC_WAIT1(); }
        else                { CPASYNC_WAIT0(); }
        __syncthreads();

        const uint32_t base = smb + (uint32_t)(c & 1) * GS_STAGE;
        #pragma unroll
        for (int ks = 0; ks < 2; ks++) {
            uint32_t bh[4][2], bl[4][2];
            #pragma unroll
            for (int half = 0; half < 2; half++) {
                int krow = ks * 16 + (lane & 15);
                int ncol = wn + half * 16 + ((lane >> 4) << 3);
                uint32_t off = base + GS_BHI + krow * 272 + ncol * 2;
                LDMX4T(bh[half*2][0], bh[half*2][1], bh[half*2+1][0], bh[half*2+1][1], off);
                LDMX4T(bl[half*2][0], bl[half*2][1], bl[half*2+1][0], bl[half*2+1][1],
                       off + (GS_BLO - GS_BHI));
            }
            #pragma unroll
            for (int mi = 0; mi < 4; mi++) {
                int r  = wm + mi * 16 + (lane & 15);
                int cl = ks * 2 + (lane >> 4);
                int p  = cl ^ ((r >> 1) & 3);
                uint32_t off = base + r * 64 + p * 16;
                uint32_t ah[4], al[4];
                LDMX4(ah[0], ah[1], ah[2], ah[3], off);
                LDMX4(al[0], al[1], al[2], al[3], off + GS_ALO);
                #pragma unroll
                for (int nj = 0; nj < 4; nj++) {
                    MMA16816(acc[mi][nj], al, bh[nj]);
                    MMA16816(acc[mi][nj], ah, bl[nj]);
                    MMA16816(acc[mi][nj], ah, bh[nj]);
                }
            }
        }
        __syncthreads();
    }

    // ---- epilogue (direct from registers) ----
    const int g = lane >> 2, t = lane & 3;
    #pragma unroll
    for (int mi = 0; mi < 4; mi++) {
        #pragma unroll
        for (int nj = 0; nj < 4; nj++) {
            int col = bn + wn + nj * 8 + t * 2;
            float b0 = bias[col], b1 = bias[col + 1];
            #pragma unroll
            for (int half = 0; half < 2; half++) {
                size_t row = (size_t)(bm + wm + mi * 16 + g + half * 8);
                size_t base2 = row * (size_t)N + col;
                float v0 = acc[mi][nj][half * 2 + 0] + b0;
                float v1 = acc[mi][nj][half * 2 + 1] + b1;
                if (EPI == 1) {
                    v0 = v0 / (1.f + __expf(-v0));
                    v1 = v1 / (1.f + __expf(-v1));
                    uint32_t hp, lp;
                    split2(v0, v1, hp, lp);
                    *(uint32_t*)(Chi + base2) = hp;
                    *(uint32_t*)(Clo + base2) = lp;
                } else {
                    if (EPI == 2) {
                        const float2 rv = *(const float2*)(res + base2);
                        v0 += rv.x; v1 += rv.y;
                    }
                    *(float2*)(C + base2) = make_float2(v0, v1);
                }
            }
        }
    }
}

// ------------------------------------------------------------ rope+split --
// rope q,k in fp32, pre-scale q by HD^-0.5, write bf16 hi/lo.
__global__ void rope_split_kernel(const float* __restrict__ qkv,
                                  __nv_bfloat16* __restrict__ qhi, __nv_bfloat16* __restrict__ qlo,
                                  __nv_bfloat16* __restrict__ khi, __nv_bfloat16* __restrict__ klo)
{
    const int half = HD_ / 2;                    // 64
    const int per  = NT_ * H_ * half;
    int idx = blockIdx.x * blockDim.x + threadIdx.x;
    if (idx >= 2 * per) return;
    const int which = idx / per;                 // 0 = q, 1 = k
    int rem   = idx - which * per;
    const int tok = rem / (H_ * half);
    const int hh  = (rem / half) % H_;
    const int d   = rem % half;
    const int t   = tok % T_;

    double rate  = pow(10000.0, -2.0 * (double)d / (double)HD_);
    double theta = (double)t * rate;
    double sd, cd;
    sincos(theta, &sd, &cd);
    const float s = (float)sd, c = (float)cd;

    const float* base = qkv + (size_t)tok * (3 * D_) + (size_t)which * D_ + hh * HD_;
    float x1v = base[d];
    float x2v = base[d + half];
    float r1 = x1v * c - x2v * s;
    float r2 = x1v * s + x2v * c;
    const float scale = 0.08838834764831843f;
    if (which == 0) { r1 *= scale; r2 *= scale; }

    __nv_bfloat16* ohi = (which == 0) ? qhi : khi;
    __nv_bfloat16* olo = (which == 0) ? qlo : klo;
    size_t ob = (size_t)tok * D_ + hh * HD_;
    __nv_bfloat16 h1 = __float2bfloat16(r1);
    __nv_bfloat16 h2 = __float2bfloat16(r2);
    ohi[ob + d]        = h1;
    ohi[ob + d + half] = h2;
    olo[ob + d]        = __float2bfloat16(r1 - __bfloat162float(h1));
    olo[ob + d + half] = __float2bfloat16(r2 - __bfloat162float(h2));
}

__global__ void vsplit_kernel(const float* __restrict__ qkv,
                              __nv_bfloat16* __restrict__ vhi, __nv_bfloat16* __restrict__ vlo)
{
    int i = blockIdx.x * blockDim.x + threadIdx.x;   // pair index
    if (i >= NT_ * D_ / 2) return;
    int row = i / (D_ / 2), col = i - row * (D_ / 2);
    float2 v = *(const float2*)(qkv + (size_t)row * (3 * D_) + 2 * D_ + 2 * col);
    uint32_t hp, lp;
    split2(v.x, v.y, hp, lp);
    ((uint32_t*)vhi)[i] = hp;
    ((uint32_t*)vlo)[i] = lp;
}

// ---------------------------------------- tensor-core flash attention -----
// Same math as round 8, staging replaced by cp.async of pre-split q/k/v.
#define QHI_OFF 0
#define QLO_OFF (128*256)
#define KHI_OFF (2*128*256)
#define KLO_OFF (2*128*256 + 64*256)
#define VHI_OFF (2*128*256 + 2*64*256)
#define VLO_OFF (2*128*256 + 2*64*256 + 64*272)
#define ATTN_SMEM (2*128*256 + 2*64*256 + 2*64*272)   // 133120 bytes

__global__ void __launch_bounds__(256, 1)
attn_mma_kernel(const __nv_bfloat16* __restrict__ qhi, const __nv_bfloat16* __restrict__ qlo,
                const __nv_bfloat16* __restrict__ khi, const __nv_bfloat16* __restrict__ klo,
                const __nv_bfloat16* __restrict__ vhi, const __nv_bfloat16* __restrict__ vlo,
                __nv_bfloat16* __restrict__ yhi, __nv_bfloat16* __restrict__ ylo)
{
    extern __shared__ char smx[];
    const uint32_t smb = sptr(smx);

    const int qb   = (T_ / 128 - 1) - blockIdx.x;   // heavy blocks first
    const int bh   = blockIdx.y;
    const int b    = bh >> 4;
    const int h    = bh & 15;
    const int tid  = threadIdx.x;
    const int lane = tid & 31;
    const int warp = tid >> 5;
    const int g    = lane >> 2;
    const int itg  = lane & 3;

    // ---- stage Q via cp.async (16 chunks/row, swizzled) ----
    {
        const size_t qgb = (size_t)(b * T_ + qb * 128) * D_ + h * HD_;
        #pragma unroll
        for (int i = 0; i < 8; i++) {
            int idx = tid + i * 256;            // 0..2047
            int r   = idx >> 4;                 // 0..127
            int c   = idx & 15;                 // 0..15
            int phys = (c & 8) | ((c & 7) ^ (r & 7));
            uint32_t dst = smb + r * 256 + phys * 16;
            size_t   src = qgb + (size_t)r * D_ + c * 8;
            CPASYNC16(dst + QHI_OFF, qhi + src);
            CPASYNC16(dst + QLO_OFF, qlo + src);
        }
        CPASYNC_COMMIT();
    }

    float o[16][4];
    #pragma unroll
    for (int i = 0; i < 16; i++)
        #pragma unroll
        for (int j = 0; j < 4; j++) o[i][j] = 0.f;
    float m[2] = {-1e30f, -1e30f};
    float l[2] = {0.f, 0.f};

    const int qbrow = qb * 128 + warp * 16;
    const int ntiles = 2 * qb + 2;

    for (int kb = 0; kb < ntiles; kb++) {
        __syncthreads();   // previous compute done with K/V smem
        const size_t kgb = (size_t)(b * T_ + kb * 64) * D_ + h * HD_;
        #pragma unroll
        for (int i = 0; i < 4; i++) {
            int idx = tid + i * 256;            // 0..1023
            int r   = idx >> 4;                 // 0..63
            int c   = idx & 15;
            int phys = (c & 8) | ((c & 7) ^ (r & 7));
            uint32_t kd = smb + KHI_OFF + r * 256 + phys * 16;
            size_t   ks = kgb + (size_t)r * D_ + c * 8;
            CPASYNC16(kd,                     khi + ks);
            CPASYNC16(kd + (KLO_OFF-KHI_OFF), klo + ks);
            uint32_t vd = smb + VHI_OFF + r * 272 + c * 16;
            CPASYNC16(vd,                     vhi + ks);
            CPASYNC16(vd + (VLO_OFF-VHI_OFF), vlo + ks);
        }
        CPASYNC_COMMIT();
        CPASYNC_WAIT0();
        __syncthreads();

        float s[8][4];
        #pragma unroll
        for (int i = 0; i < 8; i++)
            #pragma unroll
            for (int j = 0; j < 4; j++) s[i][j] = 0.f;

        #pragma unroll
        for (int ks = 0; ks < 8; ks++) {
            int qrow = warp * 16 + (lane & 15);
            int qc   = 2 * ks + (lane >> 4);
            int qph  = (qc & 8) | ((qc & 7) ^ (qrow & 7));
            uint32_t qoff = smb + QHI_OFF + qrow * 256 + qph * 16;
            uint32_t qh[4], ql[4];
            LDMX4(qh[0], qh[1], qh[2], qh[3], qoff);
            LDMX4(ql[0], ql[1], ql[2], ql[3], qoff + (QLO_OFF-QHI_OFF));

            uint32_t kbh[8][2], kbl[8][2];
            #pragma unroll
            for (int nb = 0; nb < 4; nb++) {
                int krow = nb * 16 + (lane & 7) + ((lane >> 4) << 3);
                int kc   = 2 * ks + ((lane >> 3) & 1);
                int kph  = (kc & 8) | ((kc & 7) ^ (krow & 7));
                uint32_t koff = smb + KHI_OFF + krow * 256 + kph * 16;
                LDMX4(kbh[2*nb][0], kbh[2*nb][1], kbh[2*nb+1][0], kbh[2*nb+1][1], koff);
                LDMX4(kbl[2*nb][0], kbl[2*nb][1], kbl[2*nb+1][0], kbl[2*nb+1][1],
                      koff + (KLO_OFF-KHI_OFF));
            }
            #pragma unroll
            for (int nf = 0; nf < 8; nf++) {
                MMA16816(s[nf], ql, kbh[nf]);
                MMA16816(s[nf], qh, kbl[nf]);
                MMA16816(s[nf], qh, kbh[nf]);
            }
        }

        if (kb >= 2 * qb) {
            #pragma unroll
            for (int nf = 0; nf < 8; nf++)
                #pragma unroll
                for (int c = 0; c < 4; c++) {
                    int col = kb * 64 + nf * 8 + 2 * itg + (c & 1);
                    int row = qbrow + g + (c >> 1) * 8;
                    if (col > row) s[nf][c] = -1e30f;
                }
        }

        #pragma unroll
        for (int rr = 0; rr < 2; rr++) {
            float rmax = -1e30f;
            #pragma unroll
            for (int nf = 0; nf < 8; nf++) {
                rmax = fmaxf(rmax, s[nf][rr*2]);
                rmax = fmaxf(rmax, s[nf][rr*2+1]);
            }
            rmax = fmaxf(rmax, __shfl_xor_sync(0xffffffffu, rmax, 1));
            rmax = fmaxf(rmax, __shfl_xor_sync(0xffffffffu, rmax, 2));
            float mn   = fmaxf(m[rr], rmax);
            float corr = __expf(m[rr] - mn);
            float rsum = 0.f;
            #pragma unroll
            for (int nf = 0; nf < 8; nf++) {
                float p0 = __expf(s[nf][rr*2]   - mn);
                float p1 = __expf(s[nf][rr*2+1] - mn);
                s[nf][rr*2]   = p0;
                s[nf][rr*2+1] = p1;
                rsum += p0 + p1;
            }
            rsum += __shfl_xor_sync(0xffffffffu, rsum, 1);
            rsum += __shfl_xor_sync(0xffffffffu, rsum, 2);
            l[rr] = l[rr] * corr + rsum;
            m[rr] = mn;
            #pragma unroll
            for (int nf = 0; nf < 16; nf++) {
                o[nf][rr*2]   *= corr;
                o[nf][rr*2+1] *= corr;
            }
        }

        #pragma unroll
        for (int sks = 0; sks < 4; sks++) {
            uint32_t pah[4], pal[4];
            split2(s[2*sks][0],   s[2*sks][1],   pah[0], pal[0]);
            split2(s[2*sks][2],   s[2*sks][3],   pah[1], pal[1]);
            split2(s[2*sks+1][0], s[2*sks+1][1], pah[2], pal[2]);
            split2(s[2*sks+1][2], s[2*sks+1][3], pah[3], pal[3]);
            #pragma unroll
            for (int nb = 0; nb < 8; nb++) {
                int vr = sks * 16 + (lane & 15);
                int vc = nb * 16 + ((lane >> 4) << 3);
                uint32_t voff = smb + VHI_OFF + vr * 272 + vc * 2;
                uint32_t bh0[2], bh1[2], bl0[2], bl1[2];
                LDMX4T(bh0[0], bh0[1], bh1[0], bh1[1], voff);
                LDMX4T(bl0[0], bl0[1], bl1[0], bl1[1], voff + (VLO_OFF-VHI_OFF));
                MMA16816(o[2*nb],   pal, bh0);
                MMA16816(o[2*nb],   pah, bl0);
                MMA16816(o[2*nb],   pah, bh0);
                MMA16816(o[2*nb+1], pal, bh1);
                MMA16816(o[2*nb+1], pah, bl1);
                MMA16816(o[2*nb+1], pah, bh1);
            }
        }
    }

    #pragma unroll
    for (int rr = 0; rr < 2; rr++) {
        float invl = 1.f / l[rr];
        size_t row = (size_t)(b * T_ + qbrow + g + rr * 8);
        size_t rbase = row * D_ + h * HD_;
        #pragma unroll
        for (int nf = 0; nf < 16; nf++) {
            uint32_t hp, lp;
            split2(o[nf][rr*2] * invl, o[nf][rr*2+1] * invl, hp, lp);
            *(uint32_t*)(yhi + rbase + nf * 8 + 2 * itg) = hp;
            *(uint32_t*)(ylo + rbase + nf * 8 + 2 * itg) = lp;
        }
    }
}

// ------------------------------------------------------------------- host --
extern "C" void kernel_launch(void* const* d_in, const int* in_sizes, int n_in,
                              void* d_out, int out_size)
{
    const float* x       = (const float*)d_in[0];
    const float* w_norm1 = (const float*)d_in[2];
    const float* w_qkv   = (const float*)d_in[3];
    const float* b_qkv   = (const float*)d_in[4];
    const float* w_proj  = (const float*)d_in[5];
    const float* b_proj  = (const float*)d_in[6];
    const float* w_norm2 = (const float*)d_in[7];
    const float* w_fc1   = (const float*)d_in[8];
    const float* b_fc1   = (const float*)d_in[9];
    const float* w_fc2   = (const float*)d_in[10];
    const float* b_fc2   = (const float*)d_in[11];
    float* out = (float*)d_out;

    float *qkv, *x1;
    __nv_bfloat16 *hhi, *hlo, *yhi, *ylo, *h2hi, *h2lo, *whi, *wlo;
    __nv_bfloat16 *qhi, *qlo, *khi, *klo, *vhi, *vlo;
    cudaGetSymbolAddress((void**)&qkv,  g_qkv);
    cudaGetSymbolAddress((void**)&x1,   g_x1);
    cudaGetSymbolAddress((void**)&hhi,  g_hhi);
    cudaGetSymbolAddress((void**)&hlo,  g_hlo);
    cudaGetSymbolAddress((void**)&yhi,  g_yhi);
    cudaGetSymbolAddress((void**)&ylo,  g_ylo);
    cudaGetSymbolAddress((void**)&h2hi, g_h2hi);
    cudaGetSymbolAddress((void**)&h2lo, g_h2lo);
    cudaGetSymbolAddress((void**)&whi,  g_whi);
    cudaGetSymbolAddress((void**)&wlo,  g_wlo);
    cudaGetSymbolAddress((void**)&qhi,  g_qhi);
    cudaGetSymbolAddress((void**)&qlo,  g_qlo);
    cudaGetSymbolAddress((void**)&khi,  g_khi);
    cudaGetSymbolAddress((void**)&klo,  g_klo);
    cudaGetSymbolAddress((void**)&vhi,  g_vhi);
    cudaGetSymbolAddress((void**)&vlo,  g_vlo);

    cudaFuncSetAttribute(attn_mma_kernel,
                         cudaFuncAttributeMaxDynamicSharedMemorySize, ATTN_SMEM);
    cudaFuncSetAttribute(mma_gemm_kernel<0>,
                         cudaFuncAttributeMaxDynamicSharedMemorySize, GEMM_SMEM);
    cudaFuncSetAttribute(mma_gemm_kernel<1>,
                         cudaFuncAttributeMaxDynamicSharedMemorySize, GEMM_SMEM);
    cudaFuncSetAttribute(mma_gemm_kernel<2>,
                         cudaFuncAttributeMaxDynamicSharedMemorySize, GEMM_SMEM);

    // 0. split weights ([K][N] fp32 -> bf16 hi/lo)
    wsplit_kernel<<<(12582912/2 + 255)/256, 256>>>(w_qkv,  whi + OFF_WQKV,  wlo + OFF_WQKV,  12582912/2);
    wsplit_kernel<<<( 4194304/2 + 255)/256, 256>>>(w_proj, whi + OFF_WPROJ, wlo + OFF_WPROJ,  4194304/2);
    wsplit_kernel<<<(16777216/2 + 255)/256, 256>>>(w_fc1,  whi + OFF_WFC1,  wlo + OFF_WFC1,  16777216/2);
    wsplit_kernel<<<(16777216/2 + 255)/256, 256>>>(w_fc2,  whi + OFF_WFC2,  wlo + OFF_WFC2,  16777216/2);

    // 1. h = rmsnorm(x, w_norm1) -> bf16 hi/lo
    rmsnorm_split_kernel<<<NT_, 256>>>(x, w_norm1, hhi, hlo);
    // 2. qkv = h @ w_qkv + b_qkv (fp32)
    mma_gemm_kernel<0><<<dim3(6144/128, NT_/128), 256, GEMM_SMEM>>>(
        hhi, hlo, whi + OFF_WQKV, wlo + OFF_WQKV, b_qkv, nullptr,
        qkv, nullptr, nullptr, NT_, 6144, 2048);
    // 3. rope + split q,k (q pre-scaled); split v
    rope_split_kernel<<<(2 * NT_ * H_ * (HD_/2)) / 256, 256>>>(qkv, qhi, qlo, khi, klo);
    vsplit_kernel<<<(NT_ * D_ / 2 + 255)/256, 256>>>(qkv, vhi, vlo);
    // 4. attention -> y bf16 hi/lo
    attn_mma_kernel<<<dim3(T_ / 128, B_ * H_), 256, ATTN_SMEM>>>(
        qhi, qlo, khi, klo, vhi, vlo, yhi, ylo);
    // 5. x1 = x + y @ w_proj + b_proj (fp32)
    mma_gemm_kernel<2><<<dim3(2048/128, NT_/128), 256, GEMM_SMEM>>>(
        yhi, ylo, whi + OFF_WPROJ, wlo + OFF_WPROJ, b_proj, x,
        x1, nullptr, nullptr, NT_, 2048, 2048);
    // 6. h = rmsnorm(x1, w_norm2)
    rmsnorm_split_kernel<<<NT_, 256>>>(x1, w_norm2, hhi, hlo);
    // 7. h2 = silu(h @ w_fc1 + b_fc1) -> bf16 hi/lo
    mma_gemm_kernel<1><<<dim3(8192/128, NT_/128), 256, GEMM_SMEM>>>(
        hhi, hlo, whi + OFF_WFC1, wlo + OFF_WFC1, b_fc1, nullptr,
        nullptr, h2hi, h2lo, NT_, 8192, 2048);
    // 8. out = x1 + h2 @ w_fc2 + b_fc2 (fp32)
    mma_gemm_kernel<2><<<dim3(2048/128, NT_/128), 256, GEMM_SMEM>>>(
        h2hi, h2lo, whi + OFF_WFC2, wlo + OFF_WFC2, b_fc2, x1,
        out, nullptr, nullptr, NT_, 2048, 8192);
}

// round 14
// speedup vs baseline: 3.4531x; 1.4306x over previous
#include <cuda_runtime.h>
#include <cuda_bf16.h>
#include <math.h>
#include <stdint.h>

#define D_   2048
#define H_   16
#define HD_  128
#define B_   2
#define T_   2048
#define NT_  (B_*T_)          // 4096 tokens
#define EPS_ 1e-6f

// ---------------- scratch (static device arrays; no allocation allowed) ----
__device__ float g_qkv[(size_t)NT_ * 3 * D_];            // fp32 qkv
__device__ float g_x1 [(size_t)NT_ * D_];                // fp32 x + proj
__device__ __nv_bfloat16 g_hhi [(size_t)NT_ * D_];       // rmsnorm out
__device__ __nv_bfloat16 g_hlo [(size_t)NT_ * D_];
__device__ __nv_bfloat16 g_yhi [(size_t)NT_ * D_];       // attention out
__device__ __nv_bfloat16 g_ylo [(size_t)NT_ * D_];
__device__ __nv_bfloat16 g_h2hi[(size_t)NT_ * 4 * D_];   // fc1 out
__device__ __nv_bfloat16 g_h2lo[(size_t)NT_ * 4 * D_];
__device__ __nv_bfloat16 g_qhi [(size_t)NT_ * D_];       // roped+scaled q
__device__ __nv_bfloat16 g_qlo [(size_t)NT_ * D_];
__device__ __nv_bfloat16 g_khi [(size_t)NT_ * D_];       // roped k
__device__ __nv_bfloat16 g_klo [(size_t)NT_ * D_];
__device__ __nv_bfloat16 g_vhi [(size_t)NT_ * D_];
__device__ __nv_bfloat16 g_vlo [(size_t)NT_ * D_];
__device__ float g_ropecs[T_ * 64];                      // RoPE cos table
__device__ float g_ropesn[T_ * 64];                      // RoPE sin table
// split weights, [K][N] bf16, concatenated
#define OFF_WQKV  0
#define OFF_WPROJ 12582912
#define OFF_WFC1  16777216
#define OFF_WFC2  33554432
#define WT_TOTAL  50331648
__device__ __nv_bfloat16 g_whi[WT_TOTAL];
__device__ __nv_bfloat16 g_wlo[WT_TOTAL];

// ---------------------------------------------------------------- helpers --
__device__ __forceinline__ uint32_t sptr(const void* p) {
    return (uint32_t)__cvta_generic_to_shared(p);
}

__device__ __forceinline__ void split2(float x, float y, uint32_t& hp, uint32_t& lp) {
    __nv_bfloat16 hx = __float2bfloat16(x);
    __nv_bfloat16 hy = __float2bfloat16(y);
    float rx = x - __bfloat162float(hx);
    float ry = y - __bfloat162float(hy);
    __nv_bfloat16 lx = __float2bfloat16(rx);
    __nv_bfloat16 ly = __float2bfloat16(ry);
    hp = (uint32_t)__bfloat16_as_ushort(hx) | ((uint32_t)__bfloat16_as_ushort(hy) << 16);
    lp = (uint32_t)__bfloat16_as_ushort(lx) | ((uint32_t)__bfloat16_as_ushort(ly) << 16);
}

#define LDMX4(r0,r1,r2,r3,addr) \
    asm volatile("ldmatrix.sync.aligned.m8n8.x4.shared.b16 {%0,%1,%2,%3}, [%4];" \
                 : "=r"(r0), "=r"(r1), "=r"(r2), "=r"(r3) : "r"(addr))

#define LDMX4T(r0,r1,r2,r3,addr) \
    asm volatile("ldmatrix.sync.aligned.m8n8.x4.trans.shared.b16 {%0,%1,%2,%3}, [%4];" \
                 : "=r"(r0), "=r"(r1), "=r"(r2), "=r"(r3) : "r"(addr))

#define MMA16816(c, a, b) \
    asm volatile("mma.sync.aligned.m16n8k16.row.col.f32.bf16.bf16.f32 " \
                 "{%0,%1,%2,%3}, {%4,%5,%6,%7}, {%8,%9}, {%0,%1,%2,%3};" \
                 : "+f"((c)[0]), "+f"((c)[1]), "+f"((c)[2]), "+f"((c)[3]) \
                 : "r"((a)[0]), "r"((a)[1]), "r"((a)[2]), "r"((a)[3]), \
                   "r"((b)[0]), "r"((b)[1]))

#define CPASYNC16(dst, src) \
    asm volatile("cp.async.cg.shared.global [%0], [%1], 16;" :: "r"(dst), "l"(src))
#define CPASYNC_COMMIT() asm volatile("cp.async.commit_group;" ::: "memory")
#define CPASYNC_WAIT0()  asm volatile("cp.async.wait_group 0;" ::: "memory")
#define CPASYNC_WAIT1()  asm volatile("cp.async.wait_group 1;" ::: "memory")

// ----------------------------------------------------------- weight split --
__global__ void wsplit_kernel(const float4* __restrict__ w,
                              uint2* __restrict__ whi,
                              uint2* __restrict__ wlo, int nquads)
{
    int i = blockIdx.x * blockDim.x + threadIdx.x;
    if (i >= nquads) return;
    float4 v = w[i];
    uint32_t h0, l0, h1, l1;
    split2(v.x, v.y, h0, l0);
    split2(v.z, v.w, h1, l1);
    whi[i] = make_uint2(h0, h1);
    wlo[i] = make_uint2(l0, l1);
}

// ---------------------------------------------------------- rmsnorm+split --
__global__ void rmsnorm_split_kernel(const float* __restrict__ x,
                                     const float* __restrict__ w,
                                     __nv_bfloat16* __restrict__ ohi,
                                     __nv_bfloat16* __restrict__ olo)
{
    const int row = blockIdx.x;
    const float2* xr = (const float2*)(x + (size_t)row * D_);
    const float2* w2 = (const float2*)w;
    float ss = 0.f;
    for (int i = threadIdx.x; i < D_ / 2; i += blockDim.x) {
        float2 v = xr[i];
        ss += v.x * v.x + v.y * v.y;
    }
    __shared__ float red[32];
    #pragma unroll
    for (int o = 16; o; o >>= 1) ss += __shfl_xor_sync(0xffffffffu, ss, o);
    if ((threadIdx.x & 31) == 0) red[threadIdx.x >> 5] = ss;
    __syncthreads();
    if (threadIdx.x < 32) {
        float v = (threadIdx.x < (blockDim.x >> 5)) ? red[threadIdx.x] : 0.f;
        #pragma unroll
        for (int o = 16; o; o >>= 1) v += __shfl_xor_sync(0xffffffffu, v, o);
        if (threadIdx.x == 0) red[0] = v;
    }
    __syncthreads();
    const float n   = sqrtf(red[0]) * rsqrtf((float)D_);
    const float inv = 1.f / (n + EPS_);
    uint32_t* oh = (uint32_t*)(ohi + (size_t)row * D_);
    uint32_t* ol = (uint32_t*)(olo + (size_t)row * D_);
    for (int i = threadIdx.x; i < D_ / 2; i += blockDim.x) {
        float2 v = xr[i];
        float2 ww = w2[i];
        uint32_t hp, lp;
        split2(v.x * inv * ww.x, v.y * inv * ww.y, hp, lp);
        oh[i] = hp;
        ol[i] = lp;
    }
}

// --------------------------------------------------------------- mma gemm --
// C[M,N] = A @ B + bias. A: [M][K] bf16 hi/lo. B: [K][N] bf16 hi/lo.
// EPI 0: fp32 C.  EPI 1: SiLU -> bf16 hi/lo.  EPI 2: +res -> fp32 C.
// 128x128x64 chunks, 3-stage cp.async pipeline, ONE sync per chunk.
// Per-stage smem: Ahi 16384 | Alo 16384 | Bhi 17408 | Blo 17408 = 67584 B.
#define GS_ALO 16384
#define GS_BHI 32768
#define GS_BLO 50176
#define GS_STAGE 67584
#define GEMM_SMEM (3*GS_STAGE)   // 202752

template<int EPI>
__global__ void __launch_bounds__(256)
mma_gemm_kernel(const __nv_bfloat16* __restrict__ Ah, const __nv_bfloat16* __restrict__ Al,
                const __nv_bfloat16* __restrict__ Bh, const __nv_bfloat16* __restrict__ Bl,
                const float* __restrict__ bias, const float* __restrict__ res,
                float* __restrict__ C,
                __nv_bfloat16* __restrict__ Chi, __nv_bfloat16* __restrict__ Clo,
                int M, int N, int K)
{
    extern __shared__ char sm[];
    const uint32_t smb = sptr(sm);
    const int tid  = threadIdx.x;
    const int lane = tid & 31;
    const int warp = tid >> 5;
    const int wm   = (warp >> 2) * 64;
    const int wn   = (warp & 3) * 32;
    const int bm   = blockIdx.y * 128;
    const int bn   = blockIdx.x * 128;

    float acc[4][4][4];
    #pragma unroll
    for (int i = 0; i < 4; i++)
        #pragma unroll
        for (int j = 0; j < 4; j++)
            #pragma unroll
            for (int r = 0; r < 4; r++) acc[i][j][r] = 0.f;

    const __nv_bfloat16* gAh = Ah + (size_t)bm * K;
    const __nv_bfloat16* gAl = Al + (size_t)bm * K;
    const __nv_bfloat16* gBh = Bh + bn;
    const __nv_bfloat16* gBl = Bl + bn;

    const int nchunk = K / 64;

    // stage k-chunk c into buffer (c % 3); ALWAYS commits (possibly empty).
    auto stage = [&](int c) {
        if (c < nchunk) {
            const uint32_t base = smb + (uint32_t)(c % 3) * GS_STAGE;
            const int k0 = c * 64;
            #pragma unroll
            for (int i = 0; i < 4; i++) {
                int idx = tid + i * 256;         // 0..1023
                // A: r 0..127, ch 0..7 (16B each); phys = ch ^ (r&7)
                int r  = idx >> 3, ch = idx & 7;
                uint32_t ad = base + r * 128 + (ch ^ (r & 7)) * 16;
                size_t   as = (size_t)r * K + k0 + ch * 8;
                CPASYNC16(ad,          gAh + as);
                CPASYNC16(ad + GS_ALO, gAl + as);
                // B: kr 0..63, ch 0..15 (272B row stride)
                int kr = idx >> 4, bch = idx & 15;
                uint32_t bd = base + GS_BHI + kr * 272 + bch * 16;
                size_t   bs = (size_t)(k0 + kr) * N + bch * 8;
                CPASYNC16(bd,                   gBh + bs);
                CPASYNC16(bd + (GS_BLO-GS_BHI), gBl + bs);
            }
        }
        CPASYNC_COMMIT();
    };

    stage(0);
    stage(1);

    for (int c = 0; c < nchunk; c++) {
        CPASYNC_WAIT1();        // own group c done (group c+1 may pend)
        __syncthreads();        // visibility of all threads' chunk c

        const uint32_t base = smb + (uint32_t)(c % 3) * GS_STAGE;
        #pragma unroll
        for (int ks = 0; ks < 4; ks++) {
            uint32_t bh[4][2], bl[4][2];
            #pragma unroll
            for (int half = 0; half < 2; half++) {
                int krow = ks * 16 + (lane & 15);
                int ncol = wn + half * 16 + ((lane >> 4) << 3);
                uint32_t off = base + GS_BHI + krow * 272 + ncol * 2;
                LDMX4T(bh[half*2][0], bh[half*2][1], bh[half*2+1][0], bh[half*2+1][1], off);
                LDMX4T(bl[half*2][0], bl[half*2][1], bl[half*2+1][0], bl[half*2+1][1],
                       off + (GS_BLO - GS_BHI));
            }
            #pragma unroll
            for (int mi = 0; mi < 4; mi++) {
                int r  = wm + mi * 16 + (lane & 15);
                int cl = ks * 2 + (lane >> 4);
                uint32_t off = base + r * 128 + (cl ^ (r & 7)) * 16;
                uint32_t ah[4], al[4];
                LDMX4(ah[0], ah[1], ah[2], ah[3], off);
                LDMX4(al[0], al[1], al[2], al[3], off + GS_ALO);
                #pragma unroll
                for (int nj = 0; nj < 4; nj++) {
                    MMA16816(acc[mi][nj], al, bh[nj]);
                    MMA16816(acc[mi][nj], ah, bl[nj]);
                    MMA16816(acc[mi][nj], ah, bh[nj]);
                }
            }
        }
        stage(c + 2);   // writes (c+2)%3: safe — all warps finished compute(c-1)
    }

    // ---- epilogue (direct from registers) ----
    const int g = lane >> 2, t = lane & 3;
    #pragma unroll
    for (int mi = 0; mi < 4; mi++) {
        #pragma unroll
        for (int nj = 0; nj < 4; nj++) {
            int col = bn + wn + nj * 8 + t * 2;
            float b0 = bias[col], b1 = bias[col + 1];
            #pragma unroll
            for (int half = 0; half < 2; half++) {
                size_t row = (size_t)(bm + wm + mi * 16 + g + half * 8);
                size_t base2 = row * (size_t)N + col;
                float v0 = acc[mi][nj][half * 2 + 0] + b0;
                float v1 = acc[mi][nj][half * 2 + 1] + b1;
                if (EPI == 1) {
                    v0 = v0 / (1.f + __expf(-v0));
                    v1 = v1 / (1.f + __expf(-v1));
                    uint32_t hp, lp;
                    split2(v0, v1, hp, lp);
                    *(uint32_t*)(Chi + base2) = hp;
                    *(uint32_t*)(Clo + base2) = lp;
                } else {
                    if (EPI == 2) {
                        const float2 rv = *(const float2*)(res + base2);
                        v0 += rv.x; v1 += rv.y;
                    }
                    *(float2*)(C + base2) = make_float2(v0, v1);
                }
            }
        }
    }
}

// -------------------------------------------------------------- rope table --
__global__ void rope_table_kernel(float* __restrict__ cs, float* __restrict__ sn)
{
    int i = blockIdx.x * blockDim.x + threadIdx.x;   // t*64 + d
    if (i >= T_ * 64) return;
    int t = i >> 6, d = i & 63;
    double rate  = pow(10000.0, -2.0 * (double)d / (double)HD_);
    double theta = (double)t * rate;
    double sd, cd;
    sincos(theta, &sd, &cd);
    cs[i] = (float)cd;
    sn[i] = (float)sd;
}

// ------------------------------------------------------------ rope+split --
__global__ void rope_split_kernel(const float* __restrict__ qkv,
                                  const float* __restrict__ cs, const float* __restrict__ sn,
                                  __nv_bfloat16* __restrict__ qhi, __nv_bfloat16* __restrict__ qlo,
                                  __nv_bfloat16* __restrict__ khi, __nv_bfloat16* __restrict__ klo)
{
    const int half = HD_ / 2;                    // 64
    const int per  = NT_ * H_ * half;
    int idx = blockIdx.x * blockDim.x + threadIdx.x;
    if (idx >= 2 * per) return;
    const int which = idx / per;                 // 0 = q, 1 = k
    int rem   = idx - which * per;
    const int tok = rem / (H_ * half);
    const int hh  = (rem / half) % H_;
    const int d   = rem % half;
    const int t   = tok % T_;

    const float c = cs[t * 64 + d];
    const float s = sn[t * 64 + d];

    const float* base = qkv + (size_t)tok * (3 * D_) + (size_t)which * D_ + hh * HD_;
    float x1v = base[d];
    float x2v = base[d + half];
    float r1 = x1v * c - x2v * s;
    float r2 = x1v * s + x2v * c;
    const float scale = 0.08838834764831843f;
    if (which == 0) { r1 *= scale; r2 *= scale; }

    __nv_bfloat16* ohi = (which == 0) ? qhi : khi;
    __nv_bfloat16* olo = (which == 0) ? qlo : klo;
    size_t ob = (size_t)tok * D_ + hh * HD_;
    __nv_bfloat16 h1 = __float2bfloat16(r1);
    __nv_bfloat16 h2 = __float2bfloat16(r2);
    ohi[ob + d]        = h1;
    ohi[ob + d + half] = h2;
    olo[ob + d]        = __float2bfloat16(r1 - __bfloat162float(h1));
    olo[ob + d + half] = __float2bfloat16(r2 - __bfloat162float(h2));
}

__global__ void vsplit_kernel(const float* __restrict__ qkv,
                              __nv_bfloat16* __restrict__ vhi, __nv_bfloat16* __restrict__ vlo)
{
    int i = blockIdx.x * blockDim.x + threadIdx.x;   // pair index
    if (i >= NT_ * D_ / 2) return;
    int row = i / (D_ / 2), col = i - row * (D_ / 2);
    float2 v = *(const float2*)(qkv + (size_t)row * (3 * D_) + 2 * D_ + 2 * col);
    uint32_t hp, lp;
    split2(v.x, v.y, hp, lp);
    ((uint32_t*)vhi)[i] = hp;
    ((uint32_t*)vlo)[i] = lp;
}

// ---------------------------------------- tensor-core flash attention -----
// (unchanged from round 13 — validated at 428us)
#define QHI_OFF 0
#define QLO_OFF (128*256)
#define KHI_OFF (2*128*256)
#define KLO_OFF (2*128*256 + 64*256)
#define VHI_OFF (2*128*256 + 2*64*256)
#define VLO_OFF (2*128*256 + 2*64*256 + 64*272)
#define ATTN_SMEM (2*128*256 + 2*64*256 + 2*64*272)   // 133120 bytes

__global__ void __launch_bounds__(256, 1)
attn_mma_kernel(const __nv_bfloat16* __restrict__ qhi, const __nv_bfloat16* __restrict__ qlo,
                const __nv_bfloat16* __restrict__ khi, const __nv_bfloat16* __restrict__ klo,
                const __nv_bfloat16* __restrict__ vhi, const __nv_bfloat16* __restrict__ vlo,
                __nv_bfloat16* __restrict__ yhi, __nv_bfloat16* __restrict__ ylo)
{
    extern __shared__ char smx[];
    const uint32_t smb = sptr(smx);

    const int qb   = (T_ / 128 - 1) - blockIdx.x;   // heavy blocks first
    const int bh   = blockIdx.y;
    const int b    = bh >> 4;
    const int h    = bh & 15;
    const int tid  = threadIdx.x;
    const int lane = tid & 31;
    const int warp = tid >> 5;
    const int g    = lane >> 2;
    const int itg  = lane & 3;

    {
        const size_t qgb = (size_t)(b * T_ + qb * 128) * D_ + h * HD_;
        #pragma unroll
        for (int i = 0; i < 8; i++) {
            int idx = tid + i * 256;            // 0..2047
            int r   = idx >> 4;                 // 0..127
            int c   = idx & 15;                 // 0..15
            int phys = (c & 8) | ((c & 7) ^ (r & 7));
            uint32_t dst = smb + r * 256 + phys * 16;
            size_t   src = qgb + (size_t)r * D_ + c * 8;
            CPASYNC16(dst + QHI_OFF, qhi + src);
            CPASYNC16(dst + QLO_OFF, qlo + src);
        }
        CPASYNC_COMMIT();
    }

    float o[16][4];
    #pragma unroll
    for (int i = 0; i < 16; i++)
        #pragma unroll
        for (int j = 0; j < 4; j++) o[i][j] = 0.f;
    float m[2] = {-1e30f, -1e30f};
    float l[2] = {0.f, 0.f};

    const int qbrow = qb * 128 + warp * 16;
    const int ntiles = 2 * qb + 2;

    for (int kb = 0; kb < ntiles; kb++) {
        __syncthreads();
        const size_t kgb = (size_t)(b * T_ + kb * 64) * D_ + h * HD_;
        #pragma unroll
        for (int i = 0; i < 4; i++) {
            int idx = tid + i * 256;            // 0..1023
            int r   = idx >> 4;                 // 0..63
            int c   = idx & 15;
            int phys = (c & 8) | ((c & 7) ^ (r & 7));
            uint32_t kd = smb + KHI_OFF + r * 256 + phys * 16;
            size_t   ks = kgb + (size_t)r * D_ + c * 8;
            CPASYNC16(kd,                     khi + ks);
            CPASYNC16(kd + (KLO_OFF-KHI_OFF), klo + ks);
            uint32_t vd = smb + VHI_OFF + r * 272 + c * 16;
            CPASYNC16(vd,                     vhi + ks);
            CPASYNC16(vd + (VLO_OFF-VHI_OFF), vlo + ks);
        }
        CPASYNC_COMMIT();
        CPASYNC_WAIT0();
        __syncthreads();

        float s[8][4];
        #pragma unroll
        for (int i = 0; i < 8; i++)
            #pragma unroll
            for (int j = 0; j < 4; j++) s[i][j] = 0.f;

        #pragma unroll
        for (int ks = 0; ks < 8; ks++) {
            int qrow = warp * 16 + (lane & 15);
            int qc   = 2 * ks + (lane >> 4);
            int qph  = (qc & 8) | ((qc & 7) ^ (qrow & 7));
            uint32_t qoff = smb + QHI_OFF + qrow * 256 + qph * 16;
            uint32_t qh[4], ql[4];
            LDMX4(qh[0], qh[1], qh[2], qh[3], qoff);
            LDMX4(ql[0], ql[1], ql[2], ql[3], qoff + (QLO_OFF-QHI_OFF));

            uint32_t kbh[8][2], kbl[8][2];
            #pragma unroll
            for (int nb = 0; nb < 4; nb++) {
                int krow = nb * 16 + (lane & 7) + ((lane >> 4) << 3);
                int kc   = 2 * ks + ((lane >> 3) & 1);
                int kph  = (kc & 8) | ((kc & 7) ^ (krow & 7));
                uint32_t koff = smb + KHI_OFF + krow * 256 + kph * 16;
                LDMX4(kbh[2*nb][0], kbh[2*nb][1], kbh[2*nb+1][0], kbh[2*nb+1][1], koff);
                LDMX4(kbl[2*nb][0], kbl[2*nb][1], kbl[2*nb+1][0], kbl[2*nb+1][1],
                      koff + (KLO_OFF-KHI_OFF));
            }
            #pragma unroll
            for (int nf = 0; nf < 8; nf++) {
                MMA16816(s[nf], ql, kbh[nf]);
                MMA16816(s[nf], qh, kbl[nf]);
                MMA16816(s[nf], qh, kbh[nf]);
            }
        }

        if (kb >= 2 * qb) {
            #pragma unroll
            for (int nf = 0; nf < 8; nf++)
                #pragma unroll
                for (int c = 0; c < 4; c++) {
                    int col = kb * 64 + nf * 8 + 2 * itg + (c & 1);
                    int row = qbrow + g + (c >> 1) * 8;
                    if (col > row) s[nf][c] = -1e30f;
                }
        }

        #pragma unroll
        for (int rr = 0; rr < 2; rr++) {
            float rmax = -1e30f;
            #pragma unroll
            for (int nf = 0; nf < 8; nf++) {
                rmax = fmaxf(rmax, s[nf][rr*2]);
                rmax = fmaxf(rmax, s[nf][rr*2+1]);
            }
            rmax = fmaxf(rmax, __shfl_xor_sync(0xffffffffu, rmax, 1));
            rmax = fmaxf(rmax, __shfl_xor_sync(0xffffffffu, rmax, 2));
            float mn   = fmaxf(m[rr], rmax);
            float corr = __expf(m[rr] - mn);
            float rsum = 0.f;
            #pragma unroll
            for (int nf = 0; nf < 8; nf++) {
                float p0 = __expf(s[nf][rr*2]   - mn);
                float p1 = __expf(s[nf][rr*2+1] - mn);
                s[nf][rr*2]   = p0;
                s[nf][rr*2+1] = p1;
                rsum += p0 + p1;
            }
            rsum += __shfl_xor_sync(0xffffffffu, rsum, 1);
            rsum += __shfl_xor_sync(0xffffffffu, rsum, 2);
            l[rr] = l[rr] * corr + rsum;
            m[rr] = mn;
            #pragma unroll
            for (int nf = 0; nf < 16; nf++) {
                o[nf][rr*2]   *= corr;
                o[nf][rr*2+1] *= corr;
            }
        }

        #pragma unroll
        for (int sks = 0; sks < 4; sks++) {
            uint32_t pah[4], pal[4];
            split2(s[2*sks][0],   s[2*sks][1],   pah[0], pal[0]);
            split2(s[2*sks][2],   s[2*sks][3],   pah[1], pal[1]);
            split2(s[2*sks+1][0], s[2*sks+1][1], pah[2], pal[2]);
            split2(s[2*sks+1][2], s[2*sks+1][3], pah[3], pal[3]);
            #pragma unroll
            for (int nb = 0; nb < 8; nb++) {
                int vr = sks * 16 + (lane & 15);
                int vc = nb * 16 + ((lane >> 4) << 3);
                uint32_t voff = smb + VHI_OFF + vr * 272 + vc * 2;
                uint32_t bh0[2], bh1[2], bl0[2], bl1[2];
                LDMX4T(bh0[0], bh0[1], bh1[0], bh1[1], voff);
                LDMX4T(bl0[0], bl0[1], bl1[0], bl1[1], voff + (VLO_OFF-VHI_OFF));
                MMA16816(o[2*nb],   pal, bh0);
                MMA16816(o[2*nb],   pah, bl0);
                MMA16816(o[2*nb],   pah, bh0);
                MMA16816(o[2*nb+1], pal, bh1);
                MMA16816(o[2*nb+1], pah, bl1);
                MMA16816(o[2*nb+1], pah, bh1);
            }
        }
    }

    #pragma unroll
    for (int rr = 0; rr < 2; rr++) {
        float invl = 1.f / l[rr];
        size_t row = (size_t)(b * T_ + qbrow + g + rr * 8);
        size_t rbase = row * D_ + h * HD_;
        #pragma unroll
        for (int nf = 0; nf < 16; nf++) {
            uint32_t hp, lp;
            split2(o[nf][rr*2] * invl, o[nf][rr*2+1] * invl, hp, lp);
            *(uint32_t*)(yhi + rbase + nf * 8 + 2 * itg) = hp;
            *(uint32_t*)(ylo + rbase + nf * 8 + 2 * itg) = lp;
        }
    }
}

// ------------------------------------------------------------------- host --
extern "C" void kernel_launch(void* const* d_in, const int* in_sizes, int n_in,
                              void* d_out, int out_size)
{
    const float* x       = (const float*)d_in[0];
    const float* w_norm1 = (const float*)d_in[2];
    const float* w_qkv   = (const float*)d_in[3];
    const float* b_qkv   = (const float*)d_in[4];
    const float* w_proj  = (const float*)d_in[5];
    const float* b_proj  = (const float*)d_in[6];
    const float* w_norm2 = (const float*)d_in[7];
    const float* w_fc1   = (const float*)d_in[8];
    const float* b_fc1   = (const float*)d_in[9];
    const float* w_fc2   = (const float*)d_in[10];
    const float* b_fc2   = (const float*)d_in[11];
    float* out = (float*)d_out;

    float *qkv, *x1, *rcs, *rsn;
    __nv_bfloat16 *hhi, *hlo, *yhi, *ylo, *h2hi, *h2lo, *whi, *wlo;
    __nv_bfloat16 *qhi, *qlo, *khi, *klo, *vhi, *vlo;
    cudaGetSymbolAddress((void**)&qkv,  g_qkv);
    cudaGetSymbolAddress((void**)&x1,   g_x1);
    cudaGetSymbolAddress((void**)&hhi,  g_hhi);
    cudaGetSymbolAddress((void**)&hlo,  g_hlo);
    cudaGetSymbolAddress((void**)&yhi,  g_yhi);
    cudaGetSymbolAddress((void**)&ylo,  g_ylo);
    cudaGetSymbolAddress((void**)&h2hi, g_h2hi);
    cudaGetSymbolAddress((void**)&h2lo, g_h2lo);
    cudaGetSymbolAddress((void**)&whi,  g_whi);
    cudaGetSymbolAddress((void**)&wlo,  g_wlo);
    cudaGetSymbolAddress((void**)&qhi,  g_qhi);
    cudaGetSymbolAddress((void**)&qlo,  g_qlo);
    cudaGetSymbolAddress((void**)&khi,  g_khi);
    cudaGetSymbolAddress((void**)&klo,  g_klo);
    cudaGetSymbolAddress((void**)&vhi,  g_vhi);
    cudaGetSymbolAddress((void**)&vlo,  g_vlo);
    cudaGetSymbolAddress((void**)&rcs,  g_ropecs);
    cudaGetSymbolAddress((void**)&rsn,  g_ropesn);

    cudaFuncSetAttribute(attn_mma_kernel,
                         cudaFuncAttributeMaxDynamicSharedMemorySize, ATTN_SMEM);
    cudaFuncSetAttribute(mma_gemm_kernel<0>,
                         cudaFuncAttributeMaxDynamicSharedMemorySize, GEMM_SMEM);
    cudaFuncSetAttribute(mma_gemm_kernel<1>,
                         cudaFuncAttributeMaxDynamicSharedMemorySize, GEMM_SMEM);
    cudaFuncSetAttribute(mma_gemm_kernel<2>,
                         cudaFuncAttributeMaxDynamicSharedMemorySize, GEMM_SMEM);

    // 0. split weights + rope tables (independent of activations)
    wsplit_kernel<<<(12582912/4 + 255)/256, 256>>>((const float4*)w_qkv,
        (uint2*)(whi + OFF_WQKV),  (uint2*)(wlo + OFF_WQKV),  12582912/4);
    wsplit_kernel<<<( 4194304/4 + 255)/256, 256>>>((const float4*)w_proj,
        (uint2*)(whi + OFF_WPROJ), (uint2*)(wlo + OFF_WPROJ),  4194304/4);
    wsplit_kernel<<<(16777216/4 + 255)/256, 256>>>((const float4*)w_fc1,
        (uint2*)(whi + OFF_WFC1),  (uint2*)(wlo + OFF_WFC1),  16777216/4);
    wsplit_kernel<<<(16777216/4 + 255)/256, 256>>>((const float4*)w_fc2,
        (uint2*)(whi + OFF_WFC2),  (uint2*)(wlo + OFF_WFC2),  16777216/4);
    rope_table_kernel<<<(T_ * 64 + 255)/256, 256>>>(rcs, rsn);

    // 1. h = rmsnorm(x, w_norm1) -> bf16 hi/lo
    rmsnorm_split_kernel<<<NT_, 256>>>(x, w_norm1, hhi, hlo);
    // 2. qkv = h @ w_qkv + b_qkv (fp32)
    mma_gemm_kernel<0><<<dim3(6144/128, NT_/128), 256, GEMM_SMEM>>>(
        hhi, hlo, whi + OFF_WQKV, wlo + OFF_WQKV, b_qkv, nullptr,
        qkv, nullptr, nullptr, NT_, 6144, 2048);
    // 3. rope + split q,k (q pre-scaled); split v
    rope_split_kernel<<<(2 * NT_ * H_ * (HD_/2)) / 256, 256>>>(
        qkv, rcs, rsn, qhi, qlo, khi, klo);
    vsplit_kernel<<<(NT_ * D_ / 2 + 255)/256, 256>>>(qkv, vhi, vlo);
    // 4. attention -> y bf16 hi/lo
    attn_mma_kernel<<<dim3(T_ / 128, B_ * H_), 256, ATTN_SMEM>>>(
        qhi, qlo, khi, klo, vhi, vlo, yhi, ylo);
    // 5. x1 = x + y @ w_proj + b_proj (fp32)
    mma_gemm_kernel<2><<<dim3(2048/128, NT_/128), 256, GEMM_SMEM>>>(
        yhi, ylo, whi + OFF_WPROJ, wlo + OFF_WPROJ, b_proj, x,
        x1, nullptr, nullptr, NT_, 2048, 2048);
    // 6. h = rmsnorm(x1, w_norm2)
    rmsnorm_split_kernel<<<NT_, 256>>>(x1, w_norm2, hhi, hlo);
    // 7. h2 = silu(h @ w_fc1 + b_fc1) -> bf16 hi/lo
    mma_gemm_kernel<1><<<dim3(8192/128, NT_/128), 256, GEMM_SMEM>>>(
        hhi, hlo, whi + OFF_WFC1, wlo + OFF_WFC1, b_fc1, nullptr,
        nullptr, h2hi, h2lo, NT_, 8192, 2048);
    // 8. out = x1 + h2 @ w_fc2 + b_fc2 (fp32)
    mma_gemm_kernel<2><<<dim3(2048/128, NT_/128), 256, GEMM_SMEM>>>(
        h2hi, h2lo, whi + OFF_WFC2, wlo + OFF_WFC2, b_fc2, x1,
        out, nullptr, nullptr, NT_, 2048, 8192);
}